// round 12
// baseline (speedup 1.0000x reference)
#include <cuda_runtime.h>
#include <cuda_bf16.h>
#include <cstdint>

// ============================================================================
// GUSC1 ISTA-net round 12: persistent flat-work GEMM (kills wave quantization;
// atomicAdd tile flush) + R11 fused HMMA MLPs with operand-producing epilogues.
// ============================================================================

namespace cfg {
constexpr int  BATCH = 4;
constexpr int  N     = 8192;
constexpr int  ITERS = 8;
constexpr long ROWS  = (long)BATCH * N;   // 32768
}

// ---------------------------------------------------------------------------
// Scratch (device globals)
// ---------------------------------------------------------------------------
__device__ float g_Asz [cfg::BATCH * cfg::N * 128];  // A@(s|z) fp32 [R,128]
__device__ float g_t64 [cfg::BATCH * cfg::N * 64];   // A@x / A@y  fp32 [R,64]
__device__ float g_bx  [cfg::BATCH * cfg::N * 64];
__device__ float g_sn  [cfg::BATCH * cfg::N * 64];   // snew / s  fp32 [R,64]

__device__ __nv_bfloat16 g_Ahi[(long)cfg::N * cfg::N];
__device__ __nv_bfloat16 g_Alo[(long)cfg::N * cfg::N];
__device__ __nv_bfloat16 g_Yhi [256L * cfg::N];      // x_c / y  K-major
__device__ __nv_bfloat16 g_Ylo [256L * cfg::N];
__device__ __nv_bfloat16 g_SZhi[512L * cfg::N];      // (s|z)    K-major
__device__ __nv_bfloat16 g_SZlo[512L * cfg::N];

__device__ __nv_bfloat16 g_W1h[4][128 * 64];
__device__ __nv_bfloat16 g_W1l[4][128 * 64];
__device__ __nv_bfloat16 g_W2h[4][64 * 128];
__device__ __nv_bfloat16 g_W2l[4][64 * 128];

// ---------------------------------------------------------------------------
// helpers
// ---------------------------------------------------------------------------
__device__ __forceinline__ uint32_t smem_to_u32(const void* p) {
    uint32_t a;
    asm("{ .reg .u64 t; cvta.to.shared.u64 t, %1; cvt.u32.u64 %0, t; }"
        : "=r"(a) : "l"(p));
    return a;
}
__device__ __forceinline__ void cp_async16(uint32_t dst, const void* src) {
    asm volatile("cp.async.cg.shared.global [%0], [%1], 16;" :: "r"(dst), "l"(src));
}
__device__ __forceinline__ void cp_async_commit() {
    asm volatile("cp.async.commit_group;");
}
template <int NWAIT>
__device__ __forceinline__ void cp_async_wait() {
    asm volatile("cp.async.wait_group %0;" :: "n"(NWAIT));
}
__device__ __forceinline__ void ldsm_x4(uint32_t& r0, uint32_t& r1,
                                        uint32_t& r2, uint32_t& r3, uint32_t addr) {
    asm volatile("ldmatrix.sync.aligned.m8n8.x4.shared.b16 {%0,%1,%2,%3}, [%4];"
                 : "=r"(r0), "=r"(r1), "=r"(r2), "=r"(r3) : "r"(addr));
}
__device__ __forceinline__ void mma16816(float& c0, float& c1, float& c2, float& c3,
                                         uint32_t a0, uint32_t a1, uint32_t a2, uint32_t a3,
                                         uint32_t b0, uint32_t b1) {
    asm volatile("mma.sync.aligned.m16n8k16.row.col.f32.bf16.bf16.f32 "
                 "{%0,%1,%2,%3}, {%4,%5,%6,%7}, {%8,%9}, {%0,%1,%2,%3};"
                 : "+f"(c0), "+f"(c1), "+f"(c2), "+f"(c3)
                 : "r"(a0), "r"(a1), "r"(a2), "r"(a3), "r"(b0), "r"(b1));
}
__device__ __forceinline__ uint32_t pack_bf16x2(float lo, float hi) {
    __nv_bfloat162 p = __floats2bfloat162_rn(lo, hi);
    return *reinterpret_cast<uint32_t*>(&p);
}
__device__ __forceinline__ uint32_t swz(int row, int x) {
    return (uint32_t)(row * 128 + (x ^ ((row & 7) << 4)));
}
__device__ __forceinline__ uint32_t swzH(int row, int x) {
    return (uint32_t)(row * 256 + (x ^ ((row & 7) << 4)));
}

// ---------------------------------------------------------------------------
// Persistent split-bf16 HMMA GEMM. BM=64, BN=128, KT=64, 256 thr, 2 CTAs/SM.
// Work unit = (tile, k-chunk). Each CTA owns a contiguous equal unit range;
// accumulator flushed by atomicAdd at tile boundaries (out pre-zeroed).
// ---------------------------------------------------------------------------
namespace tg {
constexpr int K   = 8192;
constexpr int KT  = 64;
constexpr int NCH = K / KT;            // 128 (7 bits)
constexpr uint32_t SZ_A = 64 * 128;
constexpr uint32_t SZ_B = 128 * 128;
constexpr uint32_t STG  = 2 * SZ_A + 2 * SZ_B;   // 49152
constexpr uint32_t SMEM_TOTAL = 2 * STG;         // 98304
}

__global__ __launch_bounds__(256, 2) void tgemm_persist(
    const __nv_bfloat16* __restrict__ Ahi, const __nv_bfloat16* __restrict__ Alo,
    const __nv_bfloat16* __restrict__ Bhi, const __nv_bfloat16* __restrict__ Blo,
    float* __restrict__ out, int cbShift, int nbN, int G)
{
    using namespace tg;
    extern __shared__ char smem[];
    const uint32_t sb  = smem_to_u32(smem);
    const int tid  = threadIdx.x;
    const int lane = tid & 31;
    const int wid  = tid >> 5;
    const int wm   = wid >> 2;
    const int wn   = wid & 3;

    const long U = (long)nbN * 128 * NCH;
    const long uStart = (U * blockIdx.x) / G;
    const long uEnd   = (U * (blockIdx.x + 1)) / G;
    if (uStart >= uEnd) return;

    const int c0r = tid >> 3;
    const int c0s = tid & 7;

    float acc[2][4][4];
#pragma unroll
    for (int i = 0; i < 2; i++)
#pragma unroll
        for (int j = 0; j < 4; j++)
#pragma unroll
            for (int q2 = 0; q2 < 4; q2++) acc[i][j][q2] = 0.f;

    const int q  = lane >> 3;
    const int r8 = lane & 7;
    const int a_row_off = wm * 32 + r8 + (q & 1) * 8;
    const int a_k_off   = (q >> 1) * 16;
    const int b_row_off = wn * 32 + r8 + (q >> 1) * 8;
    const int b_k_off   = (q & 1) * 16;

#define LOAD_UNIT(ST, UU)                                                      \
    do {                                                                       \
        const long tile_ = (UU) >> 7;                                          \
        const int  kc_   = (int)((UU) & 127);                                  \
        const long m0_   = (tile_ & 127) * 64;                                 \
        const long n0_   = (tile_ >> 7) * 128;                                 \
        const long k0_   = (long)kc_ * KT;                                     \
        const uint32_t base_ = sb + (uint32_t)(ST) * STG;                      \
        const uint32_t oA0_ = swz(c0r,      c0s * 16);                         \
        const uint32_t oA1_ = swz(c0r + 32, c0s * 16);                         \
        const long ga0_ = (m0_ + c0r)      * (long)K + k0_ + c0s * 8;          \
        const long ga1_ = (m0_ + c0r + 32) * (long)K + k0_ + c0s * 8;          \
        cp_async16(base_ + oA0_,        Ahi + ga0_);                           \
        cp_async16(base_ + oA1_,        Ahi + ga1_);                           \
        cp_async16(base_ + SZ_A + oA0_, Alo + ga0_);                           \
        cp_async16(base_ + SZ_A + oA1_, Alo + ga1_);                           \
        const uint32_t bB_ = base_ + 2 * SZ_A;                                 \
        _Pragma("unroll")                                                      \
        for (int rr_ = 0; rr_ < 4; rr_++) {                                    \
            const int brow_ = c0r + rr_ * 32;                                  \
            const uint32_t oB_ = swz(brow_, c0s * 16);                         \
            const long gb_ = (n0_ + brow_) * (long)K + k0_ + c0s * 8;          \
            cp_async16(bB_ + oB_,        Bhi + gb_);                           \
            cp_async16(bB_ + SZ_B + oB_, Blo + gb_);                           \
        }                                                                      \
        cp_async_commit();                                                     \
    } while (0)

    LOAD_UNIT(uStart & 1, uStart);

    const int CB = 1 << cbShift;
    const int cbMask = CB - 1;

    for (long u = uStart; u < uEnd; u++) {
        if (u + 1 < uEnd) {
            LOAD_UNIT((u + 1) & 1, u + 1);
            cp_async_wait<1>();
        } else {
            cp_async_wait<0>();
        }
        __syncthreads();

        const uint32_t base = sb + (uint32_t)(u & 1) * STG;
        const uint32_t aHB = base;
        const uint32_t aLB = base + SZ_A;
        const uint32_t bHB = base + 2 * SZ_A;
        const uint32_t bLB = base + 2 * SZ_A + SZ_B;

#pragma unroll
        for (int s = 0; s < 4; s++) {
            const int kb = s * 32;
            uint32_t ah[2][4], al[2][4], bh[2][4], bl[2][4];
#pragma unroll
            for (int mi = 0; mi < 2; mi++) {
                const uint32_t ad = swz(a_row_off + mi * 16, kb + a_k_off);
                ldsm_x4(ah[mi][0], ah[mi][1], ah[mi][2], ah[mi][3], aHB + ad);
                ldsm_x4(al[mi][0], al[mi][1], al[mi][2], al[mi][3], aLB + ad);
            }
#pragma unroll
            for (int ni = 0; ni < 2; ni++) {
                const uint32_t bd = swz(b_row_off + ni * 16, kb + b_k_off);
                ldsm_x4(bh[ni][0], bh[ni][1], bh[ni][2], bh[ni][3], bHB + bd);
                ldsm_x4(bl[ni][0], bl[ni][1], bl[ni][2], bl[ni][3], bLB + bd);
            }
#pragma unroll
            for (int mi = 0; mi < 2; mi++)
#pragma unroll
                for (int nj = 0; nj < 4; nj++) {
                    const int g = nj >> 1, h = (nj & 1) * 2;
                    float* c = acc[mi][nj];
                    mma16816(c[0], c[1], c[2], c[3],
                             ah[mi][0], ah[mi][1], ah[mi][2], ah[mi][3],
                             bh[g][h], bh[g][h + 1]);
                }
#pragma unroll
            for (int mi = 0; mi < 2; mi++)
#pragma unroll
                for (int nj = 0; nj < 4; nj++) {
                    const int g = nj >> 1, h = (nj & 1) * 2;
                    float* c = acc[mi][nj];
                    mma16816(c[0], c[1], c[2], c[3],
                             al[mi][0], al[mi][1], al[mi][2], al[mi][3],
                             bh[g][h], bh[g][h + 1]);
                }
#pragma unroll
            for (int mi = 0; mi < 2; mi++)
#pragma unroll
                for (int nj = 0; nj < 4; nj++) {
                    const int g = nj >> 1, h = (nj & 1) * 2;
                    float* c = acc[mi][nj];
                    mma16816(c[0], c[1], c[2], c[3],
                             ah[mi][0], ah[mi][1], ah[mi][2], ah[mi][3],
                             bl[g][h], bl[g][h + 1]);
                }
        }

        // flush at tile boundary / end of range
        if (u + 1 == uEnd || ((u + 1) & 127) == 0) {
            const long tile = u >> 7;
            const long m0 = (tile & 127) * 64;
            const long n0 = (tile >> 7) * 128;
#pragma unroll
            for (int mi = 0; mi < 2; mi++) {
                const long row = m0 + wm * 32 + mi * 16 + (lane >> 2);
#pragma unroll
                for (int nj = 0; nj < 4; nj++) {
                    const int g = (int)n0 + wn * 32 + nj * 8 + 2 * (lane & 3);
                    const int b = g >> cbShift;
                    const int c = g & cbMask;
                    float* p0 = out + ((long)b * 8192 + row) * CB + c;
                    float* p1 = out + ((long)b * 8192 + row + 8) * CB + c;
                    atomicAdd(p0,     acc[mi][nj][0]);
                    atomicAdd(p0 + 1, acc[mi][nj][1]);
                    atomicAdd(p1,     acc[mi][nj][2]);
                    atomicAdd(p1 + 1, acc[mi][nj][3]);
                    acc[mi][nj][0] = acc[mi][nj][1] = 0.f;
                    acc[mi][nj][2] = acc[mi][nj][3] = 0.f;
                }
            }
        }
        __syncthreads();
    }
#undef LOAD_UNIT
}

// ---------------------------------------------------------------------------
// Fused 2-layer MLP on HMMA (split-bf16). Unchanged from R11.
// ---------------------------------------------------------------------------
namespace fm {
constexpr uint32_t O_W1H = 0;
constexpr uint32_t O_W1L = 16384;
constexpr uint32_t O_W2H = 32768;
constexpr uint32_t O_W2L = 49152;
constexpr uint32_t O_XF  = 65536;
constexpr uint32_t O_XH  = 98304;
constexpr uint32_t O_XL  = 114688;
constexpr uint32_t O_HH  = 65536;
constexpr uint32_t O_HL  = 98304;
constexpr uint32_t O_T   = 65536;
constexpr uint32_t SMEM_TOTAL = 131072;
}

__global__ __launch_bounds__(256) void fmlp(
    const float* __restrict__ X, int ldx,
    const __nv_bfloat16* __restrict__ W1h, const __nv_bfloat16* __restrict__ W1l,
    const float* __restrict__ b1,
    const __nv_bfloat16* __restrict__ W2h, const __nv_bfloat16* __restrict__ W2l,
    const float* __restrict__ b2,
    const float* __restrict__ add,
    float* __restrict__ outF,
    __nv_bfloat16* __restrict__ outKh, __nv_bfloat16* __restrict__ outKl,
    const float* __restrict__ alphaPtr, int mode)
{
    using namespace fm;
    extern __shared__ char smem[];
    const uint32_t sb = smem_to_u32(smem);
    const int tid  = threadIdx.x;
    const int lane = tid & 31;
    const int wid  = tid >> 5;
    const long m0  = (long)blockIdx.x * 128;

    {
#pragma unroll
        for (int j = 0; j < 4; j++) {
            const int idx = tid + j * 256;
            const int row = idx >> 3, seg = idx & 7;
            const uint32_t o = swz(row, seg * 16);
            cp_async16(sb + O_W1H + o, W1h + row * 64 + seg * 8);
            cp_async16(sb + O_W1L + o, W1l + row * 64 + seg * 8);
        }
#pragma unroll
        for (int j = 0; j < 4; j++) {
            const int idx = tid + j * 256;
            const int row = idx >> 4, seg = idx & 15;
            const uint32_t o = swzH(row, seg * 16);
            cp_async16(sb + O_W2H + o, W2h + row * 128 + seg * 8);
            cp_async16(sb + O_W2L + o, W2l + row * 128 + seg * 8);
        }
#pragma unroll
        for (int j = 0; j < 8; j++) {
            const int idx = tid + j * 256;
            const int row = idx >> 4, seg = idx & 15;
            cp_async16(sb + O_XF + row * 256 + seg * 16,
                       X + (m0 + row) * (long)ldx + seg * 4);
        }
        cp_async_commit();
        cp_async_wait<0>();
        __syncthreads();
    }

#pragma unroll
    for (int j = 0; j < 16; j++) {
        const int p = tid + j * 256;
        const int row = p >> 5, kp = p & 31;
        const float2 v = *reinterpret_cast<const float2*>(smem + O_XF + row * 256 + kp * 8);
        const __nv_bfloat16 h0 = __float2bfloat16(v.x);
        const __nv_bfloat16 h1 = __float2bfloat16(v.y);
        const float l0 = v.x - __bfloat162float(h0);
        const float l1 = v.y - __bfloat162float(h1);
        const uint32_t oo = swz(row, kp * 4);
        *reinterpret_cast<uint32_t*>(smem + O_XH + oo) =
            ((uint32_t)*reinterpret_cast<const uint16_t*>(&h1) << 16) |
             (uint32_t)*reinterpret_cast<const uint16_t*>(&h0);
        *reinterpret_cast<uint32_t*>(smem + O_XL + oo) = pack_bf16x2(l0, l1);
    }
    __syncthreads();

    const int q  = lane >> 3;
    const int r8 = lane & 7;

    float acc1[4][4][4];
#pragma unroll
    for (int i = 0; i < 4; i++)
#pragma unroll
        for (int j = 0; j < 4; j++)
#pragma unroll
            for (int k = 0; k < 4; k++) acc1[i][j][k] = 0.f;
    {
        const int wm1 = wid >> 2, wn1 = wid & 3;
        const int ar = wm1 * 64 + r8 + (q & 1) * 8;
        const int ax = (q >> 1) * 16;
        const int br = wn1 * 32 + r8 + (q >> 1) * 8;
        const int bx = (q & 1) * 16;
#pragma unroll
        for (int s = 0; s < 4; s++) {
            const int kx = s * 32;
            uint32_t ah[4][4], al[4][4], bh[2][4], bl[2][4];
#pragma unroll
            for (int mi = 0; mi < 4; mi++) {
                const uint32_t ad = swz(ar + mi * 16, kx + ax);
                ldsm_x4(ah[mi][0], ah[mi][1], ah[mi][2], ah[mi][3], sb + O_XH + ad);
                ldsm_x4(al[mi][0], al[mi][1], al[mi][2], al[mi][3], sb + O_XL + ad);
            }
#pragma unroll
            for (int ni = 0; ni < 2; ni++) {
                const uint32_t bd = swz(br + ni * 16, kx + bx);
                ldsm_x4(bh[ni][0], bh[ni][1], bh[ni][2], bh[ni][3], sb + O_W1H + bd);
                ldsm_x4(bl[ni][0], bl[ni][1], bl[ni][2], bl[ni][3], sb + O_W1L + bd);
            }
#pragma unroll
            for (int mi = 0; mi < 4; mi++)
#pragma unroll
                for (int nj = 0; nj < 4; nj++) {
                    const int g = nj >> 1, h = (nj & 1) * 2;
                    float* c = acc1[mi][nj];
                    mma16816(c[0], c[1], c[2], c[3],
                             ah[mi][0], ah[mi][1], ah[mi][2], ah[mi][3],
                             bh[g][h], bh[g][h + 1]);
                    mma16816(c[0], c[1], c[2], c[3],
                             al[mi][0], al[mi][1], al[mi][2], al[mi][3],
                             bh[g][h], bh[g][h + 1]);
                    mma16816(c[0], c[1], c[2], c[3],
                             ah[mi][0], ah[mi][1], ah[mi][2], ah[mi][3],
                             bl[g][h], bl[g][h + 1]);
                }
        }
    }
    __syncthreads();

    {
        const int wm1 = wid >> 2, wn1 = wid & 3;
#pragma unroll
        for (int mi = 0; mi < 4; mi++) {
            const int row0 = wm1 * 64 + mi * 16 + (lane >> 2);
#pragma unroll
            for (int nj = 0; nj < 4; nj++) {
                const int n = wn1 * 32 + nj * 8 + 2 * (lane & 3);
                const float bb0 = __ldg(b1 + n);
                const float bb1 = __ldg(b1 + n + 1);
                float v0 = fmaxf(acc1[mi][nj][0] + bb0, 0.f);
                float v1 = fmaxf(acc1[mi][nj][1] + bb1, 0.f);
                float v2 = fmaxf(acc1[mi][nj][2] + bb0, 0.f);
                float v3 = fmaxf(acc1[mi][nj][3] + bb1, 0.f);
                const __nv_bfloat16 h0 = __float2bfloat16(v0);
                const __nv_bfloat16 h1 = __float2bfloat16(v1);
                const __nv_bfloat16 h2 = __float2bfloat16(v2);
                const __nv_bfloat16 h3 = __float2bfloat16(v3);
                const uint32_t o0 = swzH(row0,     n * 2);
                const uint32_t o1 = swzH(row0 + 8, n * 2);
                *reinterpret_cast<uint32_t*>(smem + O_HH + o0) =
                    ((uint32_t)*reinterpret_cast<const uint16_t*>(&h1) << 16) |
                     (uint32_t)*reinterpret_cast<const uint16_t*>(&h0);
                *reinterpret_cast<uint32_t*>(smem + O_HH + o1) =
                    ((uint32_t)*reinterpret_cast<const uint16_t*>(&h3) << 16) |
                     (uint32_t)*reinterpret_cast<const uint16_t*>(&h2);
                *reinterpret_cast<uint32_t*>(smem + O_HL + o0) =
                    pack_bf16x2(v0 - __bfloat162float(h0), v1 - __bfloat162float(h1));
                *reinterpret_cast<uint32_t*>(smem + O_HL + o1) =
                    pack_bf16x2(v2 - __bfloat162float(h2), v3 - __bfloat162float(h3));
            }
        }
    }
    __syncthreads();

    float acc2[2][4][4];
#pragma unroll
    for (int i = 0; i < 2; i++)
#pragma unroll
        for (int j = 0; j < 4; j++)
#pragma unroll
            for (int k = 0; k < 4; k++) acc2[i][j][k] = 0.f;
    const int wm2 = wid >> 1, wn2 = wid & 1;
    {
        const int ar = wm2 * 32 + r8 + (q & 1) * 8;
        const int ax = (q >> 1) * 16;
        const int br = wn2 * 32 + r8 + (q >> 1) * 8;
        const int bx = (q & 1) * 16;
#pragma unroll
        for (int s = 0; s < 8; s++) {
            const int kx = s * 32;
            uint32_t ah[2][4], al[2][4], bh[2][4], bl[2][4];
#pragma unroll
            for (int mi = 0; mi < 2; mi++) {
                const uint32_t ad = swzH(ar + mi * 16, kx + ax);
                ldsm_x4(ah[mi][0], ah[mi][1], ah[mi][2], ah[mi][3], sb + O_HH + ad);
                ldsm_x4(al[mi][0], al[mi][1], al[mi][2], al[mi][3], sb + O_HL + ad);
            }
#pragma unroll
            for (int ni = 0; ni < 2; ni++) {
                const uint32_t bd = swzH(br + ni * 16, kx + bx);
                ldsm_x4(bh[ni][0], bh[ni][1], bh[ni][2], bh[ni][3], sb + O_W2H + bd);
                ldsm_x4(bl[ni][0], bl[ni][1], bl[ni][2], bl[ni][3], sb + O_W2L + bd);
            }
#pragma unroll
            for (int mi = 0; mi < 2; mi++)
#pragma unroll
                for (int nj = 0; nj < 4; nj++) {
                    const int g = nj >> 1, h = (nj & 1) * 2;
                    float* c = acc2[mi][nj];
                    mma16816(c[0], c[1], c[2], c[3],
                             ah[mi][0], ah[mi][1], ah[mi][2], ah[mi][3],
                             bh[g][h], bh[g][h + 1]);
                    mma16816(c[0], c[1], c[2], c[3],
                             al[mi][0], al[mi][1], al[mi][2], al[mi][3],
                             bh[g][h], bh[g][h + 1]);
                    mma16816(c[0], c[1], c[2], c[3],
                             ah[mi][0], ah[mi][1], ah[mi][2], ah[mi][3],
                             bl[g][h], bl[g][h + 1]);
                }
        }
    }
    __syncthreads();

    const float alpha = (mode == 3) ? __ldg(alphaPtr) : 0.f;
    const uint32_t tSz = (mode == 3) ? 32768u : 16384u;
#pragma unroll
    for (int mi = 0; mi < 2; mi++) {
        const int  rl0 = wm2 * 32 + mi * 16 + (lane >> 2);
#pragma unroll
        for (int nj = 0; nj < 4; nj++) {
            const int c = wn2 * 32 + nj * 8 + 2 * (lane & 3);
            const float bb0 = __ldg(b2 + c);
            const float bb1 = __ldg(b2 + c + 1);
            float v[4];
            v[0] = acc2[mi][nj][0] + bb0;
            v[1] = acc2[mi][nj][1] + bb1;
            v[2] = acc2[mi][nj][2] + bb0;
            v[3] = acc2[mi][nj][3] + bb1;
            if (add != nullptr) {
                const float2 a0 = *reinterpret_cast<const float2*>(add + (m0 + rl0) * 64 + c);
                const float2 a1 = *reinterpret_cast<const float2*>(add + (m0 + rl0 + 8) * 64 + c);
                v[0] += a0.x; v[1] += a0.y; v[2] += a1.x; v[3] += a1.y;
            }
            if (outF != nullptr) {
                *reinterpret_cast<float2*>(outF + (m0 + rl0) * 64 + c)     = make_float2(v[0], v[1]);
                *reinterpret_cast<float2*>(outF + (m0 + rl0 + 8) * 64 + c) = make_float2(v[2], v[3]);
            }
            if (mode == 1 || mode == 3) {
#pragma unroll
                for (int e = 0; e < 4; e++) {
                    const int rl = rl0 + (e >> 1) * 8;
                    const int cc = c + (e & 1);
                    const float s = v[e];
                    const __nv_bfloat16 hi = __float2bfloat16(s);
                    *reinterpret_cast<__nv_bfloat16*>(smem + O_T + cc * 256 + rl * 2) = hi;
                    *reinterpret_cast<__nv_bfloat16*>(smem + O_T + tSz + cc * 256 + rl * 2) =
                        __float2bfloat16(s - __bfloat162float(hi));
                    if (mode == 3) {
                        const float z = (s > alpha) ? (s - alpha)
                                                    : ((s < -alpha) ? (s + alpha) : 0.f);
                        const __nv_bfloat16 zh = __float2bfloat16(z);
                        *reinterpret_cast<__nv_bfloat16*>(smem + O_T + (64 + cc) * 256 + rl * 2) = zh;
                        *reinterpret_cast<__nv_bfloat16*>(smem + O_T + tSz + (64 + cc) * 256 + rl * 2) =
                            __float2bfloat16(z - __bfloat162float(zh));
                    }
                }
            }
        }
    }

    if (mode == 1 || mode == 3) {
        __syncthreads();
        const int CB = (mode == 3) ? 128 : 64;
        const long bb = m0 >> 13;
        const long k0 = m0 & 8191;
        const int total = CB * 16 * 2;
        for (int idx = tid; idx < total; idx += 256) {
            const int arr = idx >= CB * 16;
            const int rem = arr ? idx - CB * 16 : idx;
            const int j   = rem >> 4;
            const int s16 = rem & 15;
            const uint4 val = *reinterpret_cast<const uint4*>(
                smem + O_T + (uint32_t)arr * tSz + j * 256 + s16 * 16);
            __nv_bfloat16* dst = (arr ? outKl : outKh) +
                ((long)(bb * CB + j)) * 8192 + k0 + s16 * 8;
            *reinterpret_cast<uint4*>(dst) = val;
        }
    }
}

// ---------------------------------------------------------------------------
__global__ __launch_bounds__(256) void prep_w_kernel(
    const float* __restrict__ W1, const float* __restrict__ W2,
    __nv_bfloat16* __restrict__ w1h, __nv_bfloat16* __restrict__ w1l,
    __nv_bfloat16* __restrict__ w2h, __nv_bfloat16* __restrict__ w2l)
{
    const int id = blockIdx.x * 256 + threadIdx.x;
    if (id < 8192) {
        const int n = id >> 6, k = id & 63;
        const float v = W1[k * 128 + n];
        const __nv_bfloat16 h = __float2bfloat16(v);
        w1h[id] = h;
        w1l[id] = __float2bfloat16(v - __bfloat162float(h));
    } else if (id < 16384) {
        const int i2 = id - 8192;
        const int n = i2 >> 7, k = i2 & 127;
        const float v = W2[k * 64 + n];
        const __nv_bfloat16 h = __float2bfloat16(v);
        w2h[i2] = h;
        w2l[i2] = __float2bfloat16(v - __bfloat162float(h));
    }
}

__global__ __launch_bounds__(256) void split_A_kernel(const float* __restrict__ A)
{
    const long n = (long)cfg::N * cfg::N;
    long idx = ((long)blockIdx.x * blockDim.x + threadIdx.x) * 4;
    if (idx >= n) return;
    float4 v = *reinterpret_cast<const float4*>(A + idx);
    float f[4] = {v.x, v.y, v.z, v.w};
#pragma unroll
    for (int q = 0; q < 4; q++) {
        __nv_bfloat16 hi = __float2bfloat16(f[q]);
        g_Ahi[idx + q] = hi;
        g_Alo[idx + q] = __float2bfloat16(f[q] - __bfloat162float(hi));
    }
}

__global__ __launch_bounds__(256) void split_transpose_kernel(
    const float* __restrict__ X,
    __nv_bfloat16* __restrict__ oh, __nv_bfloat16* __restrict__ ol)
{
    __shared__ float tile[32][33];
    const int k0 = blockIdx.x * 32;
    const int j0 = blockIdx.y * 32;
    const int b  = j0 / 64;
    const int c0 = j0 % 64;
    const int tx = threadIdx.x, ty = threadIdx.y;

    for (int r = ty; r < 32; r += 8)
        tile[r][tx] = X[((long)b * cfg::N + k0 + r) * 64 + c0 + tx];
    __syncthreads();
    for (int r = ty; r < 32; r += 8) {
        const float v = tile[tx][r];
        const __nv_bfloat16 hi = __float2bfloat16(v);
        const long o = (long)(j0 + r) * cfg::N + k0 + tx;
        oh[o] = hi;
        ol[o] = __float2bfloat16(v - __bfloat162float(hi));
    }
}

__global__ __launch_bounds__(256) void zero_buf_kernel(float* __restrict__ p, long n)
{
    long idx = ((long)blockIdx.x * blockDim.x + threadIdx.x) * 4;
    if (idx < n) *reinterpret_cast<float4*>(p + idx) = make_float4(0.f, 0.f, 0.f, 0.f);
}

__global__ __launch_bounds__(256) void copy_s_kernel(float* __restrict__ out)
{
    const long n = cfg::ROWS * 64;
    long idx = (long)blockIdx.x * blockDim.x + threadIdx.x;
    if (idx >= n) return;
    out[idx] = g_sn[idx];
}

// ============================================================================
extern "C" void kernel_launch(void* const* d_in, const int* in_sizes, int n_in,
                              void* d_out, int out_size)
{
    using namespace cfg;
    const float* x_c   = (const float*)d_in[0];
    const float* A     = (const float*)d_in[1];
    const float* alpha = (const float*)d_in[2];
    const float* WA1 = (const float*)d_in[3];
    const float* bA1 = (const float*)d_in[4];
    const float* WA2 = (const float*)d_in[5];
    const float* bA2 = (const float*)d_in[6];
    const float* WB1 = (const float*)d_in[7];
    const float* bB1 = (const float*)d_in[8];
    const float* WB2 = (const float*)d_in[9];
    const float* bB2 = (const float*)d_in[10];
    const float* WD1 = (const float*)d_in[11];
    const float* bD1 = (const float*)d_in[12];
    const float* WD2 = (const float*)d_in[13];
    const float* bD2 = (const float*)d_in[14];
    const float* WE1 = (const float*)d_in[15];
    const float* bE1 = (const float*)d_in[16];
    const float* WE2 = (const float*)d_in[17];
    const float* bE2 = (const float*)d_in[18];
    float* out = (float*)d_out;

    float *Asz, *t64, *bxp, *sn;
    __nv_bfloat16 *Ahi, *Alo, *Yhi, *Ylo, *SZhi, *SZlo;
    __nv_bfloat16 *W1h, *W1l, *W2h, *W2l;
    cudaGetSymbolAddress((void**)&Asz,  g_Asz);
    cudaGetSymbolAddress((void**)&t64,  g_t64);
    cudaGetSymbolAddress((void**)&bxp,  g_bx);
    cudaGetSymbolAddress((void**)&sn,   g_sn);
    cudaGetSymbolAddress((void**)&Ahi,  g_Ahi);
    cudaGetSymbolAddress((void**)&Alo,  g_Alo);
    cudaGetSymbolAddress((void**)&Yhi,  g_Yhi);
    cudaGetSymbolAddress((void**)&Ylo,  g_Ylo);
    cudaGetSymbolAddress((void**)&SZhi, g_SZhi);
    cudaGetSymbolAddress((void**)&SZlo, g_SZlo);
    cudaGetSymbolAddress((void**)&W1h,  g_W1h);
    cudaGetSymbolAddress((void**)&W1l,  g_W1l);
    cudaGetSymbolAddress((void**)&W2h,  g_W2h);
    cudaGetSymbolAddress((void**)&W2l,  g_W2l);

    int smCount = 148;
    cudaDeviceGetAttribute(&smCount, cudaDevAttrMultiProcessorCount, 0);
    const int G = 2 * smCount;

    cudaFuncSetAttribute(tgemm_persist, cudaFuncAttributeMaxDynamicSharedMemorySize,
                         tg::SMEM_TOTAL);
    cudaFuncSetAttribute(fmlp, cudaFuncAttributeMaxDynamicSharedMemorySize,
                         fm::SMEM_TOTAL);

    auto w1h = [&](int i) { return W1h + (long)i * 128 * 64; };
    auto w1l = [&](int i) { return W1l + (long)i * 128 * 64; };
    auto w2h = [&](int i) { return W2h + (long)i * 64 * 128; };
    auto w2l = [&](int i) { return W2l + (long)i * 64 * 128; };

    const dim3 blk(256);
    const dim3 gF((unsigned)(ROWS / 128), 1, 1);
    const dim3 tblk(32, 8, 1);
    const dim3 gTr64(N / 32, (BATCH * 64) / 32, 1);

    const long nT64  = ROWS * 64;
    const long nAsz  = ROWS * 128;
    const unsigned zT = (unsigned)((nT64 / 4 + 255) / 256);
    const unsigned zA = (unsigned)((nAsz / 4 + 255) / 256);

    // --- one-time prep ---
    {
        const long n4 = ((long)N * N) / 4;
        split_A_kernel<<<(unsigned)((n4 + 255) / 256), blk>>>(A);
    }
    prep_w_kernel<<<64, blk>>>(WA1, WA2, w1h(0), w1l(0), w2h(0), w2l(0));
    prep_w_kernel<<<64, blk>>>(WB1, WB2, w1h(1), w1l(1), w2h(1), w2l(1));
    prep_w_kernel<<<64, blk>>>(WD1, WD2, w1h(2), w1l(2), w2h(2), w2l(2));
    prep_w_kernel<<<64, blk>>>(WE1, WE2, w1h(3), w1l(3), w2h(3), w2l(3));

    // --- t64 = A @ x_c ---
    split_transpose_kernel<<<gTr64, tblk>>>(x_c, Yhi, Ylo);
    zero_buf_kernel<<<zT, blk>>>(t64, nT64);
    tgemm_persist<<<G, blk, tg::SMEM_TOTAL>>>(Ahi, Alo, Yhi, Ylo, t64, 6, 2, G);
    // --- bx = mlpB(t64) ---
    fmlp<<<gF, blk, fm::SMEM_TOTAL>>>(t64, 64, w1h(1), w1l(1), bB1,
                                      w2h(1), w2l(1), bB2,
                                      nullptr, bxp, nullptr, nullptr, nullptr, 0);

    for (int it = 0; it < ITERS; it++) {
        if (it > 0) {
            zero_buf_kernel<<<zA, blk>>>(Asz, nAsz);
            tgemm_persist<<<G, blk, tg::SMEM_TOTAL>>>(Ahi, Alo, SZhi, SZlo, Asz, 7, 4, G);
        } else {
            zero_buf_kernel<<<zA, blk>>>(Asz, nAsz);   // s=z=0 -> A@(s|z)=0
        }
        // y = mlpA(Asz[:, :64]) + bx  -> Y (K-major split)
        fmlp<<<gF, blk, fm::SMEM_TOTAL>>>(Asz, 128, w1h(0), w1l(0), bA1,
                                          w2h(0), w2l(0), bA2,
                                          bxp, nullptr, Yhi, Ylo, nullptr, 1);
        // t64 = A @ y
        zero_buf_kernel<<<zT, blk>>>(t64, nT64);
        tgemm_persist<<<G, blk, tg::SMEM_TOTAL>>>(Ahi, Alo, Yhi, Ylo, t64, 6, 2, G);
        // sn = mlpD(t64)
        fmlp<<<gF, blk, fm::SMEM_TOTAL>>>(t64, 64, w1h(2), w1l(2), bD1,
                                          w2h(2), w2l(2), bD2,
                                          nullptr, sn, nullptr, nullptr, nullptr, 2);
        // s = sn + mlpE(Asz[:, 64:]); z = soft(s) -> SZ, s -> sn
        fmlp<<<gF, blk, fm::SMEM_TOTAL>>>(Asz + 64, 128, w1h(3), w1l(3), bE1,
                                          w2h(3), w2l(3), bE2,
                                          sn, sn, SZhi, SZlo, alpha, 3);
    }

    // --- out[:R*64] = mlpD(s) ; out[R*64:] = s ---
    fmlp<<<gF, blk, fm::SMEM_TOTAL>>>(sn, 64, w1h(2), w1l(2), bD1,
                                      w2h(2), w2l(2), bD2,
                                      nullptr, out, nullptr, nullptr, nullptr, 4);
    {
        long n = ROWS * 64;
        copy_s_kernel<<<(unsigned)((n + 255) / 256), blk>>>(out + ROWS * 64);
    }
}

// round 13
// speedup vs baseline: 1.5722x; 1.5722x over previous
#include <cuda_runtime.h>
#include <cuda_bf16.h>
#include <cstdint>

// ============================================================================
// GUSC1 ISTA-net round 13: persistent flat-work GEMM retry with int32 work
// indexing (R12 suspected reg-spill from 64-bit index state). fmlp unchanged.
// ============================================================================

namespace cfg {
constexpr int  BATCH = 4;
constexpr int  N     = 8192;
constexpr int  ITERS = 8;
constexpr long ROWS  = (long)BATCH * N;   // 32768
}

// ---------------------------------------------------------------------------
// Scratch (device globals)
// ---------------------------------------------------------------------------
__device__ float g_Asz [cfg::BATCH * cfg::N * 128];
__device__ float g_t64 [cfg::BATCH * cfg::N * 64];
__device__ float g_bx  [cfg::BATCH * cfg::N * 64];
__device__ float g_sn  [cfg::BATCH * cfg::N * 64];

__device__ __nv_bfloat16 g_Ahi[(long)cfg::N * cfg::N];
__device__ __nv_bfloat16 g_Alo[(long)cfg::N * cfg::N];
__device__ __nv_bfloat16 g_Yhi [256L * cfg::N];
__device__ __nv_bfloat16 g_Ylo [256L * cfg::N];
__device__ __nv_bfloat16 g_SZhi[512L * cfg::N];
__device__ __nv_bfloat16 g_SZlo[512L * cfg::N];

__device__ __nv_bfloat16 g_W1h[4][128 * 64];
__device__ __nv_bfloat16 g_W1l[4][128 * 64];
__device__ __nv_bfloat16 g_W2h[4][64 * 128];
__device__ __nv_bfloat16 g_W2l[4][64 * 128];

// ---------------------------------------------------------------------------
// helpers
// ---------------------------------------------------------------------------
__device__ __forceinline__ uint32_t smem_to_u32(const void* p) {
    uint32_t a;
    asm("{ .reg .u64 t; cvta.to.shared.u64 t, %1; cvt.u32.u64 %0, t; }"
        : "=r"(a) : "l"(p));
    return a;
}
__device__ __forceinline__ void cp_async16(uint32_t dst, const void* src) {
    asm volatile("cp.async.cg.shared.global [%0], [%1], 16;" :: "r"(dst), "l"(src));
}
__device__ __forceinline__ void cp_async_commit() {
    asm volatile("cp.async.commit_group;");
}
template <int NWAIT>
__device__ __forceinline__ void cp_async_wait() {
    asm volatile("cp.async.wait_group %0;" :: "n"(NWAIT));
}
__device__ __forceinline__ void ldsm_x4(uint32_t& r0, uint32_t& r1,
                                        uint32_t& r2, uint32_t& r3, uint32_t addr) {
    asm volatile("ldmatrix.sync.aligned.m8n8.x4.shared.b16 {%0,%1,%2,%3}, [%4];"
                 : "=r"(r0), "=r"(r1), "=r"(r2), "=r"(r3) : "r"(addr));
}
__device__ __forceinline__ void mma16816(float& c0, float& c1, float& c2, float& c3,
                                         uint32_t a0, uint32_t a1, uint32_t a2, uint32_t a3,
                                         uint32_t b0, uint32_t b1) {
    asm volatile("mma.sync.aligned.m16n8k16.row.col.f32.bf16.bf16.f32 "
                 "{%0,%1,%2,%3}, {%4,%5,%6,%7}, {%8,%9}, {%0,%1,%2,%3};"
                 : "+f"(c0), "+f"(c1), "+f"(c2), "+f"(c3)
                 : "r"(a0), "r"(a1), "r"(a2), "r"(a3), "r"(b0), "r"(b1));
}
__device__ __forceinline__ uint32_t pack_bf16x2(float lo, float hi) {
    __nv_bfloat162 p = __floats2bfloat162_rn(lo, hi);
    return *reinterpret_cast<uint32_t*>(&p);
}
__device__ __forceinline__ uint32_t swz(int row, int x) {
    return (uint32_t)(row * 128 + (x ^ ((row & 7) << 4)));
}
__device__ __forceinline__ uint32_t swzH(int row, int x) {
    return (uint32_t)(row * 256 + (x ^ ((row & 7) << 4)));
}

// ---------------------------------------------------------------------------
// Persistent split-bf16 HMMA GEMM, int32 work indexing.
// BM=64, BN=128, KT=64, 256 thr, 2 CTAs/SM. Unit = (tile, kchunk); contiguous
// equal unit ranges per CTA; atomic flush at tile boundaries (out pre-zeroed).
// ---------------------------------------------------------------------------
namespace tg {
constexpr int K   = 8192;
constexpr int KT  = 64;
constexpr uint32_t SZ_A = 64 * 128;
constexpr uint32_t SZ_B = 128 * 128;
constexpr uint32_t STG  = 2 * SZ_A + 2 * SZ_B;   // 49152
constexpr uint32_t SMEM_TOTAL = 2 * STG;         // 98304
}

__global__ __launch_bounds__(256, 2) void tgemm_persist(
    const __nv_bfloat16* __restrict__ Ahi, const __nv_bfloat16* __restrict__ Alo,
    const __nv_bfloat16* __restrict__ Bhi, const __nv_bfloat16* __restrict__ Blo,
    float* __restrict__ out, int cbShift, int nbN, int G)
{
    using namespace tg;
    extern __shared__ char smem[];
    const uint32_t sb  = smem_to_u32(smem);
    const int tid  = threadIdx.x;
    const int lane = tid & 31;
    const int wid  = tid >> 5;
    const int wm   = wid >> 2;
    const int wn   = wid & 3;

    // int32 work math: U <= 65536, U*G <= ~19.4M, all element offsets < 2^27.
    const int U = nbN * 128 * 128;
    const int uStart = (int)(((long)U * blockIdx.x) / G);
    const int uEnd   = (int)(((long)U * (blockIdx.x + 1)) / G);
    if (uStart >= uEnd) return;

    const int c0r = tid >> 3;
    const int c0s = tid & 7;

    float acc[2][4][4];
#pragma unroll
    for (int i = 0; i < 2; i++)
#pragma unroll
        for (int j = 0; j < 4; j++)
#pragma unroll
            for (int q2 = 0; q2 < 4; q2++) acc[i][j][q2] = 0.f;

    const int q  = lane >> 3;
    const int r8 = lane & 7;
    const int a_row_off = wm * 32 + r8 + (q & 1) * 8;
    const int a_k_off   = (q >> 1) * 16;
    const int b_row_off = wn * 32 + r8 + (q >> 1) * 8;
    const int b_k_off   = (q & 1) * 16;

#define LOAD_UNIT(ST, UU)                                                      \
    do {                                                                       \
        const int tile_ = (UU) >> 7;                                           \
        const int m0_   = (tile_ & 127) * 64;                                  \
        const int n0_   = (tile_ >> 7) * 128;                                  \
        const int k0_   = ((UU) & 127) * KT;                                   \
        const uint32_t base_ = sb + (uint32_t)(ST) * STG;                      \
        const uint32_t oA0_ = swz(c0r,      c0s * 16);                         \
        const uint32_t oA1_ = swz(c0r + 32, c0s * 16);                         \
        const int ga0_ = (m0_ + c0r)      * K + k0_ + c0s * 8;                 \
        const int ga1_ = (m0_ + c0r + 32) * K + k0_ + c0s * 8;                 \
        cp_async16(base_ + oA0_,        Ahi + ga0_);                           \
        cp_async16(base_ + oA1_,        Ahi + ga1_);                           \
        cp_async16(base_ + SZ_A + oA0_, Alo + ga0_);                           \
        cp_async16(base_ + SZ_A + oA1_, Alo + ga1_);                           \
        const uint32_t bB_ = base_ + 2 * SZ_A;                                 \
        _Pragma("unroll")                                                      \
        for (int rr_ = 0; rr_ < 4; rr_++) {                                    \
            const int brow_ = c0r + rr_ * 32;                                  \
            const uint32_t oB_ = swz(brow_, c0s * 16);                         \
            const int gb_ = (n0_ + brow_) * K + k0_ + c0s * 8;                 \
            cp_async16(bB_ + oB_,        Bhi + gb_);                           \
            cp_async16(bB_ + SZ_B + oB_, Blo + gb_);                           \
        }                                                                      \
        cp_async_commit();                                                     \
    } while (0)

    LOAD_UNIT(uStart & 1, uStart);

    for (int u = uStart; u < uEnd; u++) {
        if (u + 1 < uEnd) {
            LOAD_UNIT((u + 1) & 1, u + 1);
            cp_async_wait<1>();
        } else {
            cp_async_wait<0>();
        }
        __syncthreads();

        const uint32_t base = sb + (uint32_t)(u & 1) * STG;
        const uint32_t aHB = base;
        const uint32_t aLB = base + SZ_A;
        const uint32_t bHB = base + 2 * SZ_A;
        const uint32_t bLB = base + 2 * SZ_A + SZ_B;

#pragma unroll
        for (int s = 0; s < 4; s++) {
            const int kb = s * 32;
            uint32_t ah[2][4], al[2][4], bh[2][4], bl[2][4];
#pragma unroll
            for (int mi = 0; mi < 2; mi++) {
                const uint32_t ad = swz(a_row_off + mi * 16, kb + a_k_off);
                ldsm_x4(ah[mi][0], ah[mi][1], ah[mi][2], ah[mi][3], aHB + ad);
                ldsm_x4(al[mi][0], al[mi][1], al[mi][2], al[mi][3], aLB + ad);
            }
#pragma unroll
            for (int ni = 0; ni < 2; ni++) {
                const uint32_t bd = swz(b_row_off + ni * 16, kb + b_k_off);
                ldsm_x4(bh[ni][0], bh[ni][1], bh[ni][2], bh[ni][3], bHB + bd);
                ldsm_x4(bl[ni][0], bl[ni][1], bl[ni][2], bl[ni][3], bLB + bd);
            }
#pragma unroll
            for (int mi = 0; mi < 2; mi++)
#pragma unroll
                for (int nj = 0; nj < 4; nj++) {
                    const int g = nj >> 1, h = (nj & 1) * 2;
                    float* c = acc[mi][nj];
                    mma16816(c[0], c[1], c[2], c[3],
                             ah[mi][0], ah[mi][1], ah[mi][2], ah[mi][3],
                             bh[g][h], bh[g][h + 1]);
                }
#pragma unroll
            for (int mi = 0; mi < 2; mi++)
#pragma unroll
                for (int nj = 0; nj < 4; nj++) {
                    const int g = nj >> 1, h = (nj & 1) * 2;
                    float* c = acc[mi][nj];
                    mma16816(c[0], c[1], c[2], c[3],
                             al[mi][0], al[mi][1], al[mi][2], al[mi][3],
                             bh[g][h], bh[g][h + 1]);
                }
#pragma unroll
            for (int mi = 0; mi < 2; mi++)
#pragma unroll
                for (int nj = 0; nj < 4; nj++) {
                    const int g = nj >> 1, h = (nj & 1) * 2;
                    float* c = acc[mi][nj];
                    mma16816(c[0], c[1], c[2], c[3],
                             ah[mi][0], ah[mi][1], ah[mi][2], ah[mi][3],
                             bl[g][h], bl[g][h + 1]);
                }
        }

        if (u + 1 == uEnd || ((u + 1) & 127) == 0) {
            const int tile = u >> 7;
            const int m0 = (tile & 127) * 64;
            const int n0 = (tile >> 7) * 128;
            const int CB = 1 << cbShift;
#pragma unroll
            for (int mi = 0; mi < 2; mi++) {
                const int row = m0 + wm * 32 + mi * 16 + (lane >> 2);
#pragma unroll
                for (int nj = 0; nj < 4; nj++) {
                    const int g = n0 + wn * 32 + nj * 8 + 2 * (lane & 3);
                    const int b = g >> cbShift;
                    const int c = g & (CB - 1);
                    const int base0 = (b * 8192 + row) * CB + c;
                    atomicAdd(out + base0,          acc[mi][nj][0]);
                    atomicAdd(out + base0 + 1,      acc[mi][nj][1]);
                    atomicAdd(out + base0 + 8 * CB,     acc[mi][nj][2]);
                    atomicAdd(out + base0 + 8 * CB + 1, acc[mi][nj][3]);
                    acc[mi][nj][0] = acc[mi][nj][1] = 0.f;
                    acc[mi][nj][2] = acc[mi][nj][3] = 0.f;
                }
            }
        }
        __syncthreads();
    }
#undef LOAD_UNIT
}

// ---------------------------------------------------------------------------
// Fused 2-layer MLP on HMMA (split-bf16). Unchanged from R11.
// ---------------------------------------------------------------------------
namespace fm {
constexpr uint32_t O_W1H = 0;
constexpr uint32_t O_W1L = 16384;
constexpr uint32_t O_W2H = 32768;
constexpr uint32_t O_W2L = 49152;
constexpr uint32_t O_XF  = 65536;
constexpr uint32_t O_XH  = 98304;
constexpr uint32_t O_XL  = 114688;
constexpr uint32_t O_HH  = 65536;
constexpr uint32_t O_HL  = 98304;
constexpr uint32_t O_T   = 65536;
constexpr uint32_t SMEM_TOTAL = 131072;
}

__global__ __launch_bounds__(256) void fmlp(
    const float* __restrict__ X, int ldx,
    const __nv_bfloat16* __restrict__ W1h, const __nv_bfloat16* __restrict__ W1l,
    const float* __restrict__ b1,
    const __nv_bfloat16* __restrict__ W2h, const __nv_bfloat16* __restrict__ W2l,
    const float* __restrict__ b2,
    const float* __restrict__ add,
    float* __restrict__ outF,
    __nv_bfloat16* __restrict__ outKh, __nv_bfloat16* __restrict__ outKl,
    const float* __restrict__ alphaPtr, int mode)
{
    using namespace fm;
    extern __shared__ char smem[];
    const uint32_t sb = smem_to_u32(smem);
    const int tid  = threadIdx.x;
    const int lane = tid & 31;
    const int wid  = tid >> 5;
    const long m0  = (long)blockIdx.x * 128;

    {
#pragma unroll
        for (int j = 0; j < 4; j++) {
            const int idx = tid + j * 256;
            const int row = idx >> 3, seg = idx & 7;
            const uint32_t o = swz(row, seg * 16);
            cp_async16(sb + O_W1H + o, W1h + row * 64 + seg * 8);
            cp_async16(sb + O_W1L + o, W1l + row * 64 + seg * 8);
        }
#pragma unroll
        for (int j = 0; j < 4; j++) {
            const int idx = tid + j * 256;
            const int row = idx >> 4, seg = idx & 15;
            const uint32_t o = swzH(row, seg * 16);
            cp_async16(sb + O_W2H + o, W2h + row * 128 + seg * 8);
            cp_async16(sb + O_W2L + o, W2l + row * 128 + seg * 8);
        }
#pragma unroll
        for (int j = 0; j < 8; j++) {
            const int idx = tid + j * 256;
            const int row = idx >> 4, seg = idx & 15;
            cp_async16(sb + O_XF + row * 256 + seg * 16,
                       X + (m0 + row) * (long)ldx + seg * 4);
        }
        cp_async_commit();
        cp_async_wait<0>();
        __syncthreads();
    }

#pragma unroll
    for (int j = 0; j < 16; j++) {
        const int p = tid + j * 256;
        const int row = p >> 5, kp = p & 31;
        const float2 v = *reinterpret_cast<const float2*>(smem + O_XF + row * 256 + kp * 8);
        const __nv_bfloat16 h0 = __float2bfloat16(v.x);
        const __nv_bfloat16 h1 = __float2bfloat16(v.y);
        const float l0 = v.x - __bfloat162float(h0);
        const float l1 = v.y - __bfloat162float(h1);
        const uint32_t oo = swz(row, kp * 4);
        *reinterpret_cast<uint32_t*>(smem + O_XH + oo) =
            ((uint32_t)*reinterpret_cast<const uint16_t*>(&h1) << 16) |
             (uint32_t)*reinterpret_cast<const uint16_t*>(&h0);
        *reinterpret_cast<uint32_t*>(smem + O_XL + oo) = pack_bf16x2(l0, l1);
    }
    __syncthreads();

    const int q  = lane >> 3;
    const int r8 = lane & 7;

    float acc1[4][4][4];
#pragma unroll
    for (int i = 0; i < 4; i++)
#pragma unroll
        for (int j = 0; j < 4; j++)
#pragma unroll
            for (int k = 0; k < 4; k++) acc1[i][j][k] = 0.f;
    {
        const int wm1 = wid >> 2, wn1 = wid & 3;
        const int ar = wm1 * 64 + r8 + (q & 1) * 8;
        const int ax = (q >> 1) * 16;
        const int br = wn1 * 32 + r8 + (q >> 1) * 8;
        const int bx = (q & 1) * 16;
#pragma unroll
        for (int s = 0; s < 4; s++) {
            const int kx = s * 32;
            uint32_t ah[4][4], al[4][4], bh[2][4], bl[2][4];
#pragma unroll
            for (int mi = 0; mi < 4; mi++) {
                const uint32_t ad = swz(ar + mi * 16, kx + ax);
                ldsm_x4(ah[mi][0], ah[mi][1], ah[mi][2], ah[mi][3], sb + O_XH + ad);
                ldsm_x4(al[mi][0], al[mi][1], al[mi][2], al[mi][3], sb + O_XL + ad);
            }
#pragma unroll
            for (int ni = 0; ni < 2; ni++) {
                const uint32_t bd = swz(br + ni * 16, kx + bx);
                ldsm_x4(bh[ni][0], bh[ni][1], bh[ni][2], bh[ni][3], sb + O_W1H + bd);
                ldsm_x4(bl[ni][0], bl[ni][1], bl[ni][2], bl[ni][3], sb + O_W1L + bd);
            }
#pragma unroll
            for (int mi = 0; mi < 4; mi++)
#pragma unroll
                for (int nj = 0; nj < 4; nj++) {
                    const int g = nj >> 1, h = (nj & 1) * 2;
                    float* c = acc1[mi][nj];
                    mma16816(c[0], c[1], c[2], c[3],
                             ah[mi][0], ah[mi][1], ah[mi][2], ah[mi][3],
                             bh[g][h], bh[g][h + 1]);
                    mma16816(c[0], c[1], c[2], c[3],
                             al[mi][0], al[mi][1], al[mi][2], al[mi][3],
                             bh[g][h], bh[g][h + 1]);
                    mma16816(c[0], c[1], c[2], c[3],
                             ah[mi][0], ah[mi][1], ah[mi][2], ah[mi][3],
                             bl[g][h], bl[g][h + 1]);
                }
        }
    }
    __syncthreads();

    {
        const int wm1 = wid >> 2, wn1 = wid & 3;
#pragma unroll
        for (int mi = 0; mi < 4; mi++) {
            const int row0 = wm1 * 64 + mi * 16 + (lane >> 2);
#pragma unroll
            for (int nj = 0; nj < 4; nj++) {
                const int n = wn1 * 32 + nj * 8 + 2 * (lane & 3);
                const float bb0 = __ldg(b1 + n);
                const float bb1 = __ldg(b1 + n + 1);
                float v0 = fmaxf(acc1[mi][nj][0] + bb0, 0.f);
                float v1 = fmaxf(acc1[mi][nj][1] + bb1, 0.f);
                float v2 = fmaxf(acc1[mi][nj][2] + bb0, 0.f);
                float v3 = fmaxf(acc1[mi][nj][3] + bb1, 0.f);
                const __nv_bfloat16 h0 = __float2bfloat16(v0);
                const __nv_bfloat16 h1 = __float2bfloat16(v1);
                const __nv_bfloat16 h2 = __float2bfloat16(v2);
                const __nv_bfloat16 h3 = __float2bfloat16(v3);
                const uint32_t o0 = swzH(row0,     n * 2);
                const uint32_t o1 = swzH(row0 + 8, n * 2);
                *reinterpret_cast<uint32_t*>(smem + O_HH + o0) =
                    ((uint32_t)*reinterpret_cast<const uint16_t*>(&h1) << 16) |
                     (uint32_t)*reinterpret_cast<const uint16_t*>(&h0);
                *reinterpret_cast<uint32_t*>(smem + O_HH + o1) =
                    ((uint32_t)*reinterpret_cast<const uint16_t*>(&h3) << 16) |
                     (uint32_t)*reinterpret_cast<const uint16_t*>(&h2);
                *reinterpret_cast<uint32_t*>(smem + O_HL + o0) =
                    pack_bf16x2(v0 - __bfloat162float(h0), v1 - __bfloat162float(h1));
                *reinterpret_cast<uint32_t*>(smem + O_HL + o1) =
                    pack_bf16x2(v2 - __bfloat162float(h2), v3 - __bfloat162float(h3));
            }
        }
    }
    __syncthreads();

    float acc2[2][4][4];
#pragma unroll
    for (int i = 0; i < 2; i++)
#pragma unroll
        for (int j = 0; j < 4; j++)
#pragma unroll
            for (int k = 0; k < 4; k++) acc2[i][j][k] = 0.f;
    const int wm2 = wid >> 1, wn2 = wid & 1;
    {
        const int ar = wm2 * 32 + r8 + (q & 1) * 8;
        const int ax = (q >> 1) * 16;
        const int br = wn2 * 32 + r8 + (q >> 1) * 8;
        const int bx = (q & 1) * 16;
#pragma unroll
        for (int s = 0; s < 8; s++) {
            const int kx = s * 32;
            uint32_t ah[2][4], al[2][4], bh[2][4], bl[2][4];
#pragma unroll
            for (int mi = 0; mi < 2; mi++) {
                const uint32_t ad = swzH(ar + mi * 16, kx + ax);
                ldsm_x4(ah[mi][0], ah[mi][1], ah[mi][2], ah[mi][3], sb + O_HH + ad);
                ldsm_x4(al[mi][0], al[mi][1], al[mi][2], al[mi][3], sb + O_HL + ad);
            }
#pragma unroll
            for (int ni = 0; ni < 2; ni++) {
                const uint32_t bd = swzH(br + ni * 16, kx + bx);
                ldsm_x4(bh[ni][0], bh[ni][1], bh[ni][2], bh[ni][3], sb + O_W2H + bd);
                ldsm_x4(bl[ni][0], bl[ni][1], bl[ni][2], bl[ni][3], sb + O_W2L + bd);
            }
#pragma unroll
            for (int mi = 0; mi < 2; mi++)
#pragma unroll
                for (int nj = 0; nj < 4; nj++) {
                    const int g = nj >> 1, h = (nj & 1) * 2;
                    float* c = acc2[mi][nj];
                    mma16816(c[0], c[1], c[2], c[3],
                             ah[mi][0], ah[mi][1], ah[mi][2], ah[mi][3],
                             bh[g][h], bh[g][h + 1]);
                    mma16816(c[0], c[1], c[2], c[3],
                             al[mi][0], al[mi][1], al[mi][2], al[mi][3],
                             bh[g][h], bh[g][h + 1]);
                    mma16816(c[0], c[1], c[2], c[3],
                             ah[mi][0], ah[mi][1], ah[mi][2], ah[mi][3],
                             bl[g][h], bl[g][h + 1]);
                }
        }
    }
    __syncthreads();

    const float alpha = (mode == 3) ? __ldg(alphaPtr) : 0.f;
    const uint32_t tSz = (mode == 3) ? 32768u : 16384u;
#pragma unroll
    for (int mi = 0; mi < 2; mi++) {
        const int  rl0 = wm2 * 32 + mi * 16 + (lane >> 2);
#pragma unroll
        for (int nj = 0; nj < 4; nj++) {
            const int c = wn2 * 32 + nj * 8 + 2 * (lane & 3);
            const float bb0 = __ldg(b2 + c);
            const float bb1 = __ldg(b2 + c + 1);
            float v[4];
            v[0] = acc2[mi][nj][0] + bb0;
            v[1] = acc2[mi][nj][1] + bb1;
            v[2] = acc2[mi][nj][2] + bb0;
            v[3] = acc2[mi][nj][3] + bb1;
            if (add != nullptr) {
                const float2 a0 = *reinterpret_cast<const float2*>(add + (m0 + rl0) * 64 + c);
                const float2 a1 = *reinterpret_cast<const float2*>(add + (m0 + rl0 + 8) * 64 + c);
                v[0] += a0.x; v[1] += a0.y; v[2] += a1.x; v[3] += a1.y;
            }
            if (outF != nullptr) {
                *reinterpret_cast<float2*>(outF + (m0 + rl0) * 64 + c)     = make_float2(v[0], v[1]);
                *reinterpret_cast<float2*>(outF + (m0 + rl0 + 8) * 64 + c) = make_float2(v[2], v[3]);
            }
            if (mode == 1 || mode == 3) {
#pragma unroll
                for (int e = 0; e < 4; e++) {
                    const int rl = rl0 + (e >> 1) * 8;
                    const int cc = c + (e & 1);
                    const float s = v[e];
                    const __nv_bfloat16 hi = __float2bfloat16(s);
                    *reinterpret_cast<__nv_bfloat16*>(smem + O_T + cc * 256 + rl * 2) = hi;
                    *reinterpret_cast<__nv_bfloat16*>(smem + O_T + tSz + cc * 256 + rl * 2) =
                        __float2bfloat16(s - __bfloat162float(hi));
                    if (mode == 3) {
                        const float z = (s > alpha) ? (s - alpha)
                                                    : ((s < -alpha) ? (s + alpha) : 0.f);
                        const __nv_bfloat16 zh = __float2bfloat16(z);
                        *reinterpret_cast<__nv_bfloat16*>(smem + O_T + (64 + cc) * 256 + rl * 2) = zh;
                        *reinterpret_cast<__nv_bfloat16*>(smem + O_T + tSz + (64 + cc) * 256 + rl * 2) =
                            __float2bfloat16(z - __bfloat162float(zh));
                    }
                }
            }
        }
    }

    if (mode == 1 || mode == 3) {
        __syncthreads();
        const int CB = (mode == 3) ? 128 : 64;
        const long bb = m0 >> 13;
        const long k0 = m0 & 8191;
        const int total = CB * 16 * 2;
        for (int idx = tid; idx < total; idx += 256) {
            const int arr = idx >= CB * 16;
            const int rem = arr ? idx - CB * 16 : idx;
            const int j   = rem >> 4;
            const int s16 = rem & 15;
            const uint4 val = *reinterpret_cast<const uint4*>(
                smem + O_T + (uint32_t)arr * tSz + j * 256 + s16 * 16);
            __nv_bfloat16* dst = (arr ? outKl : outKh) +
                ((long)(bb * CB + j)) * 8192 + k0 + s16 * 8;
            *reinterpret_cast<uint4*>(dst) = val;
        }
    }
}

// ---------------------------------------------------------------------------
__global__ __launch_bounds__(256) void prep_w_kernel(
    const float* __restrict__ W1, const float* __restrict__ W2,
    __nv_bfloat16* __restrict__ w1h, __nv_bfloat16* __restrict__ w1l,
    __nv_bfloat16* __restrict__ w2h, __nv_bfloat16* __restrict__ w2l)
{
    const int id = blockIdx.x * 256 + threadIdx.x;
    if (id < 8192) {
        const int n = id >> 6, k = id & 63;
        const float v = W1[k * 128 + n];
        const __nv_bfloat16 h = __float2bfloat16(v);
        w1h[id] = h;
        w1l[id] = __float2bfloat16(v - __bfloat162float(h));
    } else if (id < 16384) {
        const int i2 = id - 8192;
        const int n = i2 >> 7, k = i2 & 127;
        const float v = W2[k * 64 + n];
        const __nv_bfloat16 h = __float2bfloat16(v);
        w2h[i2] = h;
        w2l[i2] = __float2bfloat16(v - __bfloat162float(h));
    }
}

__global__ __launch_bounds__(256) void split_A_kernel(const float* __restrict__ A)
{
    const long n = (long)cfg::N * cfg::N;
    long idx = ((long)blockIdx.x * blockDim.x + threadIdx.x) * 4;
    if (idx >= n) return;
    float4 v = *reinterpret_cast<const float4*>(A + idx);
    float f[4] = {v.x, v.y, v.z, v.w};
#pragma unroll
    for (int q = 0; q < 4; q++) {
        __nv_bfloat16 hi = __float2bfloat16(f[q]);
        g_Ahi[idx + q] = hi;
        g_Alo[idx + q] = __float2bfloat16(f[q] - __bfloat162float(hi));
    }
}

__global__ __launch_bounds__(256) void split_transpose_kernel(
    const float* __restrict__ X,
    __nv_bfloat16* __restrict__ oh, __nv_bfloat16* __restrict__ ol)
{
    __shared__ float tile[32][33];
    const int k0 = blockIdx.x * 32;
    const int j0 = blockIdx.y * 32;
    const int b  = j0 / 64;
    const int c0 = j0 % 64;
    const int tx = threadIdx.x, ty = threadIdx.y;

    for (int r = ty; r < 32; r += 8)
        tile[r][tx] = X[((long)b * cfg::N + k0 + r) * 64 + c0 + tx];
    __syncthreads();
    for (int r = ty; r < 32; r += 8) {
        const float v = tile[tx][r];
        const __nv_bfloat16 hi = __float2bfloat16(v);
        const long o = (long)(j0 + r) * cfg::N + k0 + tx;
        oh[o] = hi;
        ol[o] = __float2bfloat16(v - __bfloat162float(hi));
    }
}

__global__ __launch_bounds__(256) void zero_buf_kernel(float* __restrict__ p, long n)
{
    long idx = ((long)blockIdx.x * blockDim.x + threadIdx.x) * 4;
    if (idx < n) *reinterpret_cast<float4*>(p + idx) = make_float4(0.f, 0.f, 0.f, 0.f);
}

__global__ __launch_bounds__(256) void copy_s_kernel(float* __restrict__ out)
{
    const long n = cfg::ROWS * 64;
    long idx = (long)blockIdx.x * blockDim.x + threadIdx.x;
    if (idx >= n) return;
    out[idx] = g_sn[idx];
}

// ============================================================================
extern "C" void kernel_launch(void* const* d_in, const int* in_sizes, int n_in,
                              void* d_out, int out_size)
{
    using namespace cfg;
    const float* x_c   = (const float*)d_in[0];
    const float* A     = (const float*)d_in[1];
    const float* alpha = (const float*)d_in[2];
    const float* WA1 = (const float*)d_in[3];
    const float* bA1 = (const float*)d_in[4];
    const float* WA2 = (const float*)d_in[5];
    const float* bA2 = (const float*)d_in[6];
    const float* WB1 = (const float*)d_in[7];
    const float* bB1 = (const float*)d_in[8];
    const float* WB2 = (const float*)d_in[9];
    const float* bB2 = (const float*)d_in[10];
    const float* WD1 = (const float*)d_in[11];
    const float* bD1 = (const float*)d_in[12];
    const float* WD2 = (const float*)d_in[13];
    const float* bD2 = (const float*)d_in[14];
    const float* WE1 = (const float*)d_in[15];
    const float* bE1 = (const float*)d_in[16];
    const float* WE2 = (const float*)d_in[17];
    const float* bE2 = (const float*)d_in[18];
    float* out = (float*)d_out;

    float *Asz, *t64, *bxp, *sn;
    __nv_bfloat16 *Ahi, *Alo, *Yhi, *Ylo, *SZhi, *SZlo;
    __nv_bfloat16 *W1h, *W1l, *W2h, *W2l;
    cudaGetSymbolAddress((void**)&Asz,  g_Asz);
    cudaGetSymbolAddress((void**)&t64,  g_t64);
    cudaGetSymbolAddress((void**)&bxp,  g_bx);
    cudaGetSymbolAddress((void**)&sn,   g_sn);
    cudaGetSymbolAddress((void**)&Ahi,  g_Ahi);
    cudaGetSymbolAddress((void**)&Alo,  g_Alo);
    cudaGetSymbolAddress((void**)&Yhi,  g_Yhi);
    cudaGetSymbolAddress((void**)&Ylo,  g_Ylo);
    cudaGetSymbolAddress((void**)&SZhi, g_SZhi);
    cudaGetSymbolAddress((void**)&SZlo, g_SZlo);
    cudaGetSymbolAddress((void**)&W1h,  g_W1h);
    cudaGetSymbolAddress((void**)&W1l,  g_W1l);
    cudaGetSymbolAddress((void**)&W2h,  g_W2h);
    cudaGetSymbolAddress((void**)&W2l,  g_W2l);

    int smCount = 148;
    cudaDeviceGetAttribute(&smCount, cudaDevAttrMultiProcessorCount, 0);
    const int G = 2 * smCount;

    cudaFuncSetAttribute(tgemm_persist, cudaFuncAttributeMaxDynamicSharedMemorySize,
                         tg::SMEM_TOTAL);
    cudaFuncSetAttribute(fmlp, cudaFuncAttributeMaxDynamicSharedMemorySize,
                         fm::SMEM_TOTAL);

    auto w1h = [&](int i) { return W1h + (long)i * 128 * 64; };
    auto w1l = [&](int i) { return W1l + (long)i * 128 * 64; };
    auto w2h = [&](int i) { return W2h + (long)i * 64 * 128; };
    auto w2l = [&](int i) { return W2l + (long)i * 64 * 128; };

    const dim3 blk(256);
    const dim3 gF((unsigned)(ROWS / 128), 1, 1);
    const dim3 tblk(32, 8, 1);
    const dim3 gTr64(N / 32, (BATCH * 64) / 32, 1);

    const long nT64  = ROWS * 64;
    const long nAsz  = ROWS * 128;
    const unsigned zT = (unsigned)((nT64 / 4 + 255) / 256);
    const unsigned zA = (unsigned)((nAsz / 4 + 255) / 256);

    // --- one-time prep ---
    {
        const long n4 = ((long)N * N) / 4;
        split_A_kernel<<<(unsigned)((n4 + 255) / 256), blk>>>(A);
    }
    prep_w_kernel<<<64, blk>>>(WA1, WA2, w1h(0), w1l(0), w2h(0), w2l(0));
    prep_w_kernel<<<64, blk>>>(WB1, WB2, w1h(1), w1l(1), w2h(1), w2l(1));
    prep_w_kernel<<<64, blk>>>(WD1, WD2, w1h(2), w1l(2), w2h(2), w2l(2));
    prep_w_kernel<<<64, blk>>>(WE1, WE2, w1h(3), w1l(3), w2h(3), w2l(3));

    // --- t64 = A @ x_c ---
    split_transpose_kernel<<<gTr64, tblk>>>(x_c, Yhi, Ylo);
    zero_buf_kernel<<<zT, blk>>>(t64, nT64);
    tgemm_persist<<<G, blk, tg::SMEM_TOTAL>>>(Ahi, Alo, Yhi, Ylo, t64, 6, 2, G);
    // --- bx = mlpB(t64) ---
    fmlp<<<gF, blk, fm::SMEM_TOTAL>>>(t64, 64, w1h(1), w1l(1), bB1,
                                      w2h(1), w2l(1), bB2,
                                      nullptr, bxp, nullptr, nullptr, nullptr, 0);

    for (int it = 0; it < ITERS; it++) {
        zero_buf_kernel<<<zA, blk>>>(Asz, nAsz);
        if (it > 0) {
            tgemm_persist<<<G, blk, tg::SMEM_TOTAL>>>(Ahi, Alo, SZhi, SZlo, Asz, 7, 4, G);
        }
        // y = mlpA(Asz[:, :64]) + bx  -> Y (K-major split)
        fmlp<<<gF, blk, fm::SMEM_TOTAL>>>(Asz, 128, w1h(0), w1l(0), bA1,
                                          w2h(0), w2l(0), bA2,
                                          bxp, nullptr, Yhi, Ylo, nullptr, 1);
        // t64 = A @ y
        zero_buf_kernel<<<zT, blk>>>(t64, nT64);
        tgemm_persist<<<G, blk, tg::SMEM_TOTAL>>>(Ahi, Alo, Yhi, Ylo, t64, 6, 2, G);
        // sn = mlpD(t64)
        fmlp<<<gF, blk, fm::SMEM_TOTAL>>>(t64, 64, w1h(2), w1l(2), bD1,
                                          w2h(2), w2l(2), bD2,
                                          nullptr, sn, nullptr, nullptr, nullptr, 2);
        // s = sn + mlpE(Asz[:, 64:]); z = soft(s) -> SZ, s -> sn
        fmlp<<<gF, blk, fm::SMEM_TOTAL>>>(Asz + 64, 128, w1h(3), w1l(3), bE1,
                                          w2h(3), w2l(3), bE2,
                                          sn, sn, SZhi, SZlo, alpha, 3);
    }

    // --- out[:R*64] = mlpD(s) ; out[R*64:] = s ---
    fmlp<<<gF, blk, fm::SMEM_TOTAL>>>(sn, 64, w1h(2), w1l(2), bD1,
                                      w2h(2), w2l(2), bD2,
                                      nullptr, out, nullptr, nullptr, nullptr, 4);
    {
        long n = ROWS * 64;
        copy_s_kernel<<<(unsigned)((n + 255) / 256), blk>>>(out + ROWS * 64);
    }
}

// round 14
// speedup vs baseline: 1.5771x; 1.0031x over previous
#include <cuda_runtime.h>
#include <cuda_bf16.h>
#include <cstdint>

// ============================================================================
// GUSC1 ISTA-net round 14: R13 persistent GEMM + fmlp with fused buffer
// zeroing (kills 15 zero launches) and direct s-output (kills copy_s).
// ============================================================================

namespace cfg {
constexpr int  BATCH = 4;
constexpr int  N     = 8192;
constexpr int  ITERS = 8;
constexpr long ROWS  = (long)BATCH * N;   // 32768
}

// ---------------------------------------------------------------------------
// Scratch (device globals)
// ---------------------------------------------------------------------------
__device__ float g_Asz [cfg::BATCH * cfg::N * 128];
__device__ float g_t64 [cfg::BATCH * cfg::N * 64];
__device__ float g_bx  [cfg::BATCH * cfg::N * 64];
__device__ float g_sn  [cfg::BATCH * cfg::N * 64];

__device__ __nv_bfloat16 g_Ahi[(long)cfg::N * cfg::N];
__device__ __nv_bfloat16 g_Alo[(long)cfg::N * cfg::N];
__device__ __nv_bfloat16 g_Yhi [256L * cfg::N];
__device__ __nv_bfloat16 g_Ylo [256L * cfg::N];
__device__ __nv_bfloat16 g_SZhi[512L * cfg::N];
__device__ __nv_bfloat16 g_SZlo[512L * cfg::N];

__device__ __nv_bfloat16 g_W1h[4][128 * 64];
__device__ __nv_bfloat16 g_W1l[4][128 * 64];
__device__ __nv_bfloat16 g_W2h[4][64 * 128];
__device__ __nv_bfloat16 g_W2l[4][64 * 128];

// ---------------------------------------------------------------------------
// helpers
// ---------------------------------------------------------------------------
__device__ __forceinline__ uint32_t smem_to_u32(const void* p) {
    uint32_t a;
    asm("{ .reg .u64 t; cvta.to.shared.u64 t, %1; cvt.u32.u64 %0, t; }"
        : "=r"(a) : "l"(p));
    return a;
}
__device__ __forceinline__ void cp_async16(uint32_t dst, const void* src) {
    asm volatile("cp.async.cg.shared.global [%0], [%1], 16;" :: "r"(dst), "l"(src));
}
__device__ __forceinline__ void cp_async_commit() {
    asm volatile("cp.async.commit_group;");
}
template <int NWAIT>
__device__ __forceinline__ void cp_async_wait() {
    asm volatile("cp.async.wait_group %0;" :: "n"(NWAIT));
}
__device__ __forceinline__ void ldsm_x4(uint32_t& r0, uint32_t& r1,
                                        uint32_t& r2, uint32_t& r3, uint32_t addr) {
    asm volatile("ldmatrix.sync.aligned.m8n8.x4.shared.b16 {%0,%1,%2,%3}, [%4];"
                 : "=r"(r0), "=r"(r1), "=r"(r2), "=r"(r3) : "r"(addr));
}
__device__ __forceinline__ void mma16816(float& c0, float& c1, float& c2, float& c3,
                                         uint32_t a0, uint32_t a1, uint32_t a2, uint32_t a3,
                                         uint32_t b0, uint32_t b1) {
    asm volatile("mma.sync.aligned.m16n8k16.row.col.f32.bf16.bf16.f32 "
                 "{%0,%1,%2,%3}, {%4,%5,%6,%7}, {%8,%9}, {%0,%1,%2,%3};"
                 : "+f"(c0), "+f"(c1), "+f"(c2), "+f"(c3)
                 : "r"(a0), "r"(a1), "r"(a2), "r"(a3), "r"(b0), "r"(b1));
}
__device__ __forceinline__ uint32_t pack_bf16x2(float lo, float hi) {
    __nv_bfloat162 p = __floats2bfloat162_rn(lo, hi);
    return *reinterpret_cast<uint32_t*>(&p);
}
__device__ __forceinline__ uint32_t swz(int row, int x) {
    return (uint32_t)(row * 128 + (x ^ ((row & 7) << 4)));
}
__device__ __forceinline__ uint32_t swzH(int row, int x) {
    return (uint32_t)(row * 256 + (x ^ ((row & 7) << 4)));
}

// ---------------------------------------------------------------------------
// Persistent split-bf16 HMMA GEMM (R13, unchanged).
// ---------------------------------------------------------------------------
namespace tg {
constexpr int K   = 8192;
constexpr int KT  = 64;
constexpr uint32_t SZ_A = 64 * 128;
constexpr uint32_t SZ_B = 128 * 128;
constexpr uint32_t STG  = 2 * SZ_A + 2 * SZ_B;   // 49152
constexpr uint32_t SMEM_TOTAL = 2 * STG;         // 98304
}

__global__ __launch_bounds__(256, 2) void tgemm_persist(
    const __nv_bfloat16* __restrict__ Ahi, const __nv_bfloat16* __restrict__ Alo,
    const __nv_bfloat16* __restrict__ Bhi, const __nv_bfloat16* __restrict__ Blo,
    float* __restrict__ out, int cbShift, int nbN, int G)
{
    using namespace tg;
    extern __shared__ char smem[];
    const uint32_t sb  = smem_to_u32(smem);
    const int tid  = threadIdx.x;
    const int lane = tid & 31;
    const int wid  = tid >> 5;
    const int wm   = wid >> 2;
    const int wn   = wid & 3;

    const int U = nbN * 128 * 128;
    const int uStart = (int)(((long)U * blockIdx.x) / G);
    const int uEnd   = (int)(((long)U * (blockIdx.x + 1)) / G);
    if (uStart >= uEnd) return;

    const int c0r = tid >> 3;
    const int c0s = tid & 7;

    float acc[2][4][4];
#pragma unroll
    for (int i = 0; i < 2; i++)
#pragma unroll
        for (int j = 0; j < 4; j++)
#pragma unroll
            for (int q2 = 0; q2 < 4; q2++) acc[i][j][q2] = 0.f;

    const int q  = lane >> 3;
    const int r8 = lane & 7;
    const int a_row_off = wm * 32 + r8 + (q & 1) * 8;
    const int a_k_off   = (q >> 1) * 16;
    const int b_row_off = wn * 32 + r8 + (q >> 1) * 8;
    const int b_k_off   = (q & 1) * 16;

#define LOAD_UNIT(ST, UU)                                                      \
    do {                                                                       \
        const int tile_ = (UU) >> 7;                                           \
        const int m0_   = (tile_ & 127) * 64;                                  \
        const int n0_   = (tile_ >> 7) * 128;                                  \
        const int k0_   = ((UU) & 127) * KT;                                   \
        const uint32_t base_ = sb + (uint32_t)(ST) * STG;                      \
        const uint32_t oA0_ = swz(c0r,      c0s * 16);                         \
        const uint32_t oA1_ = swz(c0r + 32, c0s * 16);                         \
        const int ga0_ = (m0_ + c0r)      * K + k0_ + c0s * 8;                 \
        const int ga1_ = (m0_ + c0r + 32) * K + k0_ + c0s * 8;                 \
        cp_async16(base_ + oA0_,        Ahi + ga0_);                           \
        cp_async16(base_ + oA1_,        Ahi + ga1_);                           \
        cp_async16(base_ + SZ_A + oA0_, Alo + ga0_);                           \
        cp_async16(base_ + SZ_A + oA1_, Alo + ga1_);                           \
        const uint32_t bB_ = base_ + 2 * SZ_A;                                 \
        _Pragma("unroll")                                                      \
        for (int rr_ = 0; rr_ < 4; rr_++) {                                    \
            const int brow_ = c0r + rr_ * 32;                                  \
            const uint32_t oB_ = swz(brow_, c0s * 16);                         \
            const int gb_ = (n0_ + brow_) * K + k0_ + c0s * 8;                 \
            cp_async16(bB_ + oB_,        Bhi + gb_);                           \
            cp_async16(bB_ + SZ_B + oB_, Blo + gb_);                           \
        }                                                                      \
        cp_async_commit();                                                     \
    } while (0)

    LOAD_UNIT(uStart & 1, uStart);

    for (int u = uStart; u < uEnd; u++) {
        if (u + 1 < uEnd) {
            LOAD_UNIT((u + 1) & 1, u + 1);
            cp_async_wait<1>();
        } else {
            cp_async_wait<0>();
        }
        __syncthreads();

        const uint32_t base = sb + (uint32_t)(u & 1) * STG;
        const uint32_t aHB = base;
        const uint32_t aLB = base + SZ_A;
        const uint32_t bHB = base + 2 * SZ_A;
        const uint32_t bLB = base + 2 * SZ_A + SZ_B;

#pragma unroll
        for (int s = 0; s < 4; s++) {
            const int kb = s * 32;
            uint32_t ah[2][4], al[2][4], bh[2][4], bl[2][4];
#pragma unroll
            for (int mi = 0; mi < 2; mi++) {
                const uint32_t ad = swz(a_row_off + mi * 16, kb + a_k_off);
                ldsm_x4(ah[mi][0], ah[mi][1], ah[mi][2], ah[mi][3], aHB + ad);
                ldsm_x4(al[mi][0], al[mi][1], al[mi][2], al[mi][3], aLB + ad);
            }
#pragma unroll
            for (int ni = 0; ni < 2; ni++) {
                const uint32_t bd = swz(b_row_off + ni * 16, kb + b_k_off);
                ldsm_x4(bh[ni][0], bh[ni][1], bh[ni][2], bh[ni][3], bHB + bd);
                ldsm_x4(bl[ni][0], bl[ni][1], bl[ni][2], bl[ni][3], bLB + bd);
            }
#pragma unroll
            for (int mi = 0; mi < 2; mi++)
#pragma unroll
                for (int nj = 0; nj < 4; nj++) {
                    const int g = nj >> 1, h = (nj & 1) * 2;
                    float* c = acc[mi][nj];
                    mma16816(c[0], c[1], c[2], c[3],
                             ah[mi][0], ah[mi][1], ah[mi][2], ah[mi][3],
                             bh[g][h], bh[g][h + 1]);
                }
#pragma unroll
            for (int mi = 0; mi < 2; mi++)
#pragma unroll
                for (int nj = 0; nj < 4; nj++) {
                    const int g = nj >> 1, h = (nj & 1) * 2;
                    float* c = acc[mi][nj];
                    mma16816(c[0], c[1], c[2], c[3],
                             al[mi][0], al[mi][1], al[mi][2], al[mi][3],
                             bh[g][h], bh[g][h + 1]);
                }
#pragma unroll
            for (int mi = 0; mi < 2; mi++)
#pragma unroll
                for (int nj = 0; nj < 4; nj++) {
                    const int g = nj >> 1, h = (nj & 1) * 2;
                    float* c = acc[mi][nj];
                    mma16816(c[0], c[1], c[2], c[3],
                             ah[mi][0], ah[mi][1], ah[mi][2], ah[mi][3],
                             bl[g][h], bl[g][h + 1]);
                }
        }

        if (u + 1 == uEnd || ((u + 1) & 127) == 0) {
            const int tile = u >> 7;
            const int m0 = (tile & 127) * 64;
            const int n0 = (tile >> 7) * 128;
            const int CB = 1 << cbShift;
#pragma unroll
            for (int mi = 0; mi < 2; mi++) {
                const int row = m0 + wm * 32 + mi * 16 + (lane >> 2);
#pragma unroll
                for (int nj = 0; nj < 4; nj++) {
                    const int g = n0 + wn * 32 + nj * 8 + 2 * (lane & 3);
                    const int b = g >> cbShift;
                    const int c = g & (CB - 1);
                    const int base0 = (b * 8192 + row) * CB + c;
                    atomicAdd(out + base0,              acc[mi][nj][0]);
                    atomicAdd(out + base0 + 1,          acc[mi][nj][1]);
                    atomicAdd(out + base0 + 8 * CB,     acc[mi][nj][2]);
                    atomicAdd(out + base0 + 8 * CB + 1, acc[mi][nj][3]);
                    acc[mi][nj][0] = acc[mi][nj][1] = 0.f;
                    acc[mi][nj][2] = acc[mi][nj][3] = 0.f;
                }
            }
        }
        __syncthreads();
    }
#undef LOAD_UNIT
}

// ---------------------------------------------------------------------------
// Fused 2-layer MLP on HMMA (split-bf16) + optional fused buffer zeroing.
// ---------------------------------------------------------------------------
namespace fm {
constexpr uint32_t O_W1H = 0;
constexpr uint32_t O_W1L = 16384;
constexpr uint32_t O_W2H = 32768;
constexpr uint32_t O_W2L = 49152;
constexpr uint32_t O_XF  = 65536;
constexpr uint32_t O_XH  = 98304;
constexpr uint32_t O_XL  = 114688;
constexpr uint32_t O_HH  = 65536;
constexpr uint32_t O_HL  = 98304;
constexpr uint32_t O_T   = 65536;
constexpr uint32_t SMEM_TOTAL = 131072;
}

__global__ __launch_bounds__(256) void fmlp(
    const float* __restrict__ X, int ldx,
    const __nv_bfloat16* __restrict__ W1h, const __nv_bfloat16* __restrict__ W1l,
    const float* __restrict__ b1,
    const __nv_bfloat16* __restrict__ W2h, const __nv_bfloat16* __restrict__ W2l,
    const float* __restrict__ b2,
    const float* __restrict__ add,
    float* __restrict__ outF,
    __nv_bfloat16* __restrict__ outKh, __nv_bfloat16* __restrict__ outKl,
    const float* __restrict__ alphaPtr, int mode,
    float* __restrict__ zbuf, int zcols)
{
    using namespace fm;
    extern __shared__ char smem[];
    const uint32_t sb = smem_to_u32(smem);
    const int tid  = threadIdx.x;
    const int lane = tid & 31;
    const int wid  = tid >> 5;
    const long m0  = (long)blockIdx.x * 128;

    {
#pragma unroll
        for (int j = 0; j < 4; j++) {
            const int idx = tid + j * 256;
            const int row = idx >> 3, seg = idx & 7;
            const uint32_t o = swz(row, seg * 16);
            cp_async16(sb + O_W1H + o, W1h + row * 64 + seg * 8);
            cp_async16(sb + O_W1L + o, W1l + row * 64 + seg * 8);
        }
#pragma unroll
        for (int j = 0; j < 4; j++) {
            const int idx = tid + j * 256;
            const int row = idx >> 4, seg = idx & 15;
            const uint32_t o = swzH(row, seg * 16);
            cp_async16(sb + O_W2H + o, W2h + row * 128 + seg * 8);
            cp_async16(sb + O_W2L + o, W2l + row * 128 + seg * 8);
        }
#pragma unroll
        for (int j = 0; j < 8; j++) {
            const int idx = tid + j * 256;
            const int row = idx >> 4, seg = idx & 15;
            cp_async16(sb + O_XF + row * 256 + seg * 16,
                       X + (m0 + row) * (long)ldx + seg * 4);
        }
        cp_async_commit();
        cp_async_wait<0>();
        __syncthreads();
    }

#pragma unroll
    for (int j = 0; j < 16; j++) {
        const int p = tid + j * 256;
        const int row = p >> 5, kp = p & 31;
        const float2 v = *reinterpret_cast<const float2*>(smem + O_XF + row * 256 + kp * 8);
        const __nv_bfloat16 h0 = __float2bfloat16(v.x);
        const __nv_bfloat16 h1 = __float2bfloat16(v.y);
        const float l0 = v.x - __bfloat162float(h0);
        const float l1 = v.y - __bfloat162float(h1);
        const uint32_t oo = swz(row, kp * 4);
        *reinterpret_cast<uint32_t*>(smem + O_XH + oo) =
            ((uint32_t)*reinterpret_cast<const uint16_t*>(&h1) << 16) |
             (uint32_t)*reinterpret_cast<const uint16_t*>(&h0);
        *reinterpret_cast<uint32_t*>(smem + O_XL + oo) = pack_bf16x2(l0, l1);
    }
    __syncthreads();

    // fused zeroing of the CTA's rows in zbuf (consumed-before, written-after
    // in stream order; see host comments).
    if (zbuf != nullptr) {
        float4* zp = reinterpret_cast<float4*>(zbuf + m0 * zcols);
        const int tot = 128 * zcols / 4;
        const float4 z4 = make_float4(0.f, 0.f, 0.f, 0.f);
        for (int i = tid; i < tot; i += 256) zp[i] = z4;
    }

    const int q  = lane >> 3;
    const int r8 = lane & 7;

    float acc1[4][4][4];
#pragma unroll
    for (int i = 0; i < 4; i++)
#pragma unroll
        for (int j = 0; j < 4; j++)
#pragma unroll
            for (int k = 0; k < 4; k++) acc1[i][j][k] = 0.f;
    {
        const int wm1 = wid >> 2, wn1 = wid & 3;
        const int ar = wm1 * 64 + r8 + (q & 1) * 8;
        const int ax = (q >> 1) * 16;
        const int br = wn1 * 32 + r8 + (q >> 1) * 8;
        const int bx = (q & 1) * 16;
#pragma unroll
        for (int s = 0; s < 4; s++) {
            const int kx = s * 32;
            uint32_t ah[4][4], al[4][4], bh[2][4], bl[2][4];
#pragma unroll
            for (int mi = 0; mi < 4; mi++) {
                const uint32_t ad = swz(ar + mi * 16, kx + ax);
                ldsm_x4(ah[mi][0], ah[mi][1], ah[mi][2], ah[mi][3], sb + O_XH + ad);
                ldsm_x4(al[mi][0], al[mi][1], al[mi][2], al[mi][3], sb + O_XL + ad);
            }
#pragma unroll
            for (int ni = 0; ni < 2; ni++) {
                const uint32_t bd = swz(br + ni * 16, kx + bx);
                ldsm_x4(bh[ni][0], bh[ni][1], bh[ni][2], bh[ni][3], sb + O_W1H + bd);
                ldsm_x4(bl[ni][0], bl[ni][1], bl[ni][2], bl[ni][3], sb + O_W1L + bd);
            }
#pragma unroll
            for (int mi = 0; mi < 4; mi++)
#pragma unroll
                for (int nj = 0; nj < 4; nj++) {
                    const int g = nj >> 1, h = (nj & 1) * 2;
                    float* c = acc1[mi][nj];
                    mma16816(c[0], c[1], c[2], c[3],
                             ah[mi][0], ah[mi][1], ah[mi][2], ah[mi][3],
                             bh[g][h], bh[g][h + 1]);
                    mma16816(c[0], c[1], c[2], c[3],
                             al[mi][0], al[mi][1], al[mi][2], al[mi][3],
                             bh[g][h], bh[g][h + 1]);
                    mma16816(c[0], c[1], c[2], c[3],
                             ah[mi][0], ah[mi][1], ah[mi][2], ah[mi][3],
                             bl[g][h], bl[g][h + 1]);
                }
        }
    }
    __syncthreads();

    {
        const int wm1 = wid >> 2, wn1 = wid & 3;
#pragma unroll
        for (int mi = 0; mi < 4; mi++) {
            const int row0 = wm1 * 64 + mi * 16 + (lane >> 2);
#pragma unroll
            for (int nj = 0; nj < 4; nj++) {
                const int n = wn1 * 32 + nj * 8 + 2 * (lane & 3);
                const float bb0 = __ldg(b1 + n);
                const float bb1 = __ldg(b1 + n + 1);
                float v0 = fmaxf(acc1[mi][nj][0] + bb0, 0.f);
                float v1 = fmaxf(acc1[mi][nj][1] + bb1, 0.f);
                float v2 = fmaxf(acc1[mi][nj][2] + bb0, 0.f);
                float v3 = fmaxf(acc1[mi][nj][3] + bb1, 0.f);
                const __nv_bfloat16 h0 = __float2bfloat16(v0);
                const __nv_bfloat16 h1 = __float2bfloat16(v1);
                const __nv_bfloat16 h2 = __float2bfloat16(v2);
                const __nv_bfloat16 h3 = __float2bfloat16(v3);
                const uint32_t o0 = swzH(row0,     n * 2);
                const uint32_t o1 = swzH(row0 + 8, n * 2);
                *reinterpret_cast<uint32_t*>(smem + O_HH + o0) =
                    ((uint32_t)*reinterpret_cast<const uint16_t*>(&h1) << 16) |
                     (uint32_t)*reinterpret_cast<const uint16_t*>(&h0);
                *reinterpret_cast<uint32_t*>(smem + O_HH + o1) =
                    ((uint32_t)*reinterpret_cast<const uint16_t*>(&h3) << 16) |
                     (uint32_t)*reinterpret_cast<const uint16_t*>(&h2);
                *reinterpret_cast<uint32_t*>(smem + O_HL + o0) =
                    pack_bf16x2(v0 - __bfloat162float(h0), v1 - __bfloat162float(h1));
                *reinterpret_cast<uint32_t*>(smem + O_HL + o1) =
                    pack_bf16x2(v2 - __bfloat162float(h2), v3 - __bfloat162float(h3));
            }
        }
    }
    __syncthreads();

    float acc2[2][4][4];
#pragma unroll
    for (int i = 0; i < 2; i++)
#pragma unroll
        for (int j = 0; j < 4; j++)
#pragma unroll
            for (int k = 0; k < 4; k++) acc2[i][j][k] = 0.f;
    const int wm2 = wid >> 1, wn2 = wid & 1;
    {
        const int ar = wm2 * 32 + r8 + (q & 1) * 8;
        const int ax = (q >> 1) * 16;
        const int br = wn2 * 32 + r8 + (q >> 1) * 8;
        const int bx = (q & 1) * 16;
#pragma unroll
        for (int s = 0; s < 8; s++) {
            const int kx = s * 32;
            uint32_t ah[2][4], al[2][4], bh[2][4], bl[2][4];
#pragma unroll
            for (int mi = 0; mi < 2; mi++) {
                const uint32_t ad = swzH(ar + mi * 16, kx + ax);
                ldsm_x4(ah[mi][0], ah[mi][1], ah[mi][2], ah[mi][3], sb + O_HH + ad);
                ldsm_x4(al[mi][0], al[mi][1], al[mi][2], al[mi][3], sb + O_HL + ad);
            }
#pragma unroll
            for (int ni = 0; ni < 2; ni++) {
                const uint32_t bd = swzH(br + ni * 16, kx + bx);
                ldsm_x4(bh[ni][0], bh[ni][1], bh[ni][2], bh[ni][3], sb + O_W2H + bd);
                ldsm_x4(bl[ni][0], bl[ni][1], bl[ni][2], bl[ni][3], sb + O_W2L + bd);
            }
#pragma unroll
            for (int mi = 0; mi < 2; mi++)
#pragma unroll
                for (int nj = 0; nj < 4; nj++) {
                    const int g = nj >> 1, h = (nj & 1) * 2;
                    float* c = acc2[mi][nj];
                    mma16816(c[0], c[1], c[2], c[3],
                             ah[mi][0], ah[mi][1], ah[mi][2], ah[mi][3],
                             bh[g][h], bh[g][h + 1]);
                    mma16816(c[0], c[1], c[2], c[3],
                             al[mi][0], al[mi][1], al[mi][2], al[mi][3],
                             bh[g][h], bh[g][h + 1]);
                    mma16816(c[0], c[1], c[2], c[3],
                             ah[mi][0], ah[mi][1], ah[mi][2], ah[mi][3],
                             bl[g][h], bl[g][h + 1]);
                }
        }
    }
    __syncthreads();

    const float alpha = (mode == 3) ? __ldg(alphaPtr) : 0.f;
    const uint32_t tSz = (mode == 3) ? 32768u : 16384u;
#pragma unroll
    for (int mi = 0; mi < 2; mi++) {
        const int  rl0 = wm2 * 32 + mi * 16 + (lane >> 2);
#pragma unroll
        for (int nj = 0; nj < 4; nj++) {
            const int c = wn2 * 32 + nj * 8 + 2 * (lane & 3);
            const float bb0 = __ldg(b2 + c);
            const float bb1 = __ldg(b2 + c + 1);
            float v[4];
            v[0] = acc2[mi][nj][0] + bb0;
            v[1] = acc2[mi][nj][1] + bb1;
            v[2] = acc2[mi][nj][2] + bb0;
            v[3] = acc2[mi][nj][3] + bb1;
            if (add != nullptr) {
                const float2 a0 = *reinterpret_cast<const float2*>(add + (m0 + rl0) * 64 + c);
                const float2 a1 = *reinterpret_cast<const float2*>(add + (m0 + rl0 + 8) * 64 + c);
                v[0] += a0.x; v[1] += a0.y; v[2] += a1.x; v[3] += a1.y;
            }
            if (outF != nullptr) {
                *reinterpret_cast<float2*>(outF + (m0 + rl0) * 64 + c)     = make_float2(v[0], v[1]);
                *reinterpret_cast<float2*>(outF + (m0 + rl0 + 8) * 64 + c) = make_float2(v[2], v[3]);
            }
            if (mode == 1 || mode == 3) {
#pragma unroll
                for (int e = 0; e < 4; e++) {
                    const int rl = rl0 + (e >> 1) * 8;
                    const int cc = c + (e & 1);
                    const float s = v[e];
                    const __nv_bfloat16 hi = __float2bfloat16(s);
                    *reinterpret_cast<__nv_bfloat16*>(smem + O_T + cc * 256 + rl * 2) = hi;
                    *reinterpret_cast<__nv_bfloat16*>(smem + O_T + tSz + cc * 256 + rl * 2) =
                        __float2bfloat16(s - __bfloat162float(hi));
                    if (mode == 3) {
                        const float z = (s > alpha) ? (s - alpha)
                                                    : ((s < -alpha) ? (s + alpha) : 0.f);
                        const __nv_bfloat16 zh = __float2bfloat16(z);
                        *reinterpret_cast<__nv_bfloat16*>(smem + O_T + (64 + cc) * 256 + rl * 2) = zh;
                        *reinterpret_cast<__nv_bfloat16*>(smem + O_T + tSz + (64 + cc) * 256 + rl * 2) =
                            __float2bfloat16(z - __bfloat162float(zh));
                    }
                }
            }
        }
    }

    if (mode == 1 || mode == 3) {
        __syncthreads();
        const int CB = (mode == 3) ? 128 : 64;
        const long bb = m0 >> 13;
        const long k0 = m0 & 8191;
        const int total = CB * 16 * 2;
        for (int idx = tid; idx < total; idx += 256) {
            const int arr = idx >= CB * 16;
            const int rem = arr ? idx - CB * 16 : idx;
            const int j   = rem >> 4;
            const int s16 = rem & 15;
            const uint4 val = *reinterpret_cast<const uint4*>(
                smem + O_T + (uint32_t)arr * tSz + j * 256 + s16 * 16);
            __nv_bfloat16* dst = (arr ? outKl : outKh) +
                ((long)(bb * CB + j)) * 8192 + k0 + s16 * 8;
            *reinterpret_cast<uint4*>(dst) = val;
        }
    }
}

// ---------------------------------------------------------------------------
__global__ __launch_bounds__(256) void prep_w_kernel(
    const float* __restrict__ W1, const float* __restrict__ W2,
    __nv_bfloat16* __restrict__ w1h, __nv_bfloat16* __restrict__ w1l,
    __nv_bfloat16* __restrict__ w2h, __nv_bfloat16* __restrict__ w2l)
{
    const int id = blockIdx.x * 256 + threadIdx.x;
    if (id < 8192) {
        const int n = id >> 6, k = id & 63;
        const float v = W1[k * 128 + n];
        const __nv_bfloat16 h = __float2bfloat16(v);
        w1h[id] = h;
        w1l[id] = __float2bfloat16(v - __bfloat162float(h));
    } else if (id < 16384) {
        const int i2 = id - 8192;
        const int n = i2 >> 7, k = i2 & 127;
        const float v = W2[k * 64 + n];
        const __nv_bfloat16 h = __float2bfloat16(v);
        w2h[i2] = h;
        w2l[i2] = __float2bfloat16(v - __bfloat162float(h));
    }
}

__global__ __launch_bounds__(256) void split_A_kernel(const float* __restrict__ A)
{
    const long n = (long)cfg::N * cfg::N;
    long idx = ((long)blockIdx.x * blockDim.x + threadIdx.x) * 4;
    if (idx >= n) return;
    float4 v = *reinterpret_cast<const float4*>(A + idx);
    float f[4] = {v.x, v.y, v.z, v.w};
#pragma unroll
    for (int q = 0; q < 4; q++) {
        __nv_bfloat16 hi = __float2bfloat16(f[q]);
        g_Ahi[idx + q] = hi;
        g_Alo[idx + q] = __float2bfloat16(f[q] - __bfloat162float(hi));
    }
}

__global__ __launch_bounds__(256) void split_transpose_kernel(
    const float* __restrict__ X,
    __nv_bfloat16* __restrict__ oh, __nv_bfloat16* __restrict__ ol)
{
    __shared__ float tile[32][33];
    const int k0 = blockIdx.x * 32;
    const int j0 = blockIdx.y * 32;
    const int b  = j0 / 64;
    const int c0 = j0 % 64;
    const int tx = threadIdx.x, ty = threadIdx.y;

    for (int r = ty; r < 32; r += 8)
        tile[r][tx] = X[((long)b * cfg::N + k0 + r) * 64 + c0 + tx];
    __syncthreads();
    for (int r = ty; r < 32; r += 8) {
        const float v = tile[tx][r];
        const __nv_bfloat16 hi = __float2bfloat16(v);
        const long o = (long)(j0 + r) * cfg::N + k0 + tx;
        oh[o] = hi;
        ol[o] = __float2bfloat16(v - __bfloat162float(hi));
    }
}

__global__ __launch_bounds__(256) void zero_buf_kernel(float* __restrict__ p, long n)
{
    long idx = ((long)blockIdx.x * blockDim.x + threadIdx.x) * 4;
    if (idx < n) *reinterpret_cast<float4*>(p + idx) = make_float4(0.f, 0.f, 0.f, 0.f);
}

// ============================================================================
extern "C" void kernel_launch(void* const* d_in, const int* in_sizes, int n_in,
                              void* d_out, int out_size)
{
    using namespace cfg;
    const float* x_c   = (const float*)d_in[0];
    const float* A     = (const float*)d_in[1];
    const float* alpha = (const float*)d_in[2];
    const float* WA1 = (const float*)d_in[3];
    const float* bA1 = (const float*)d_in[4];
    const float* WA2 = (const float*)d_in[5];
    const float* bA2 = (const float*)d_in[6];
    const float* WB1 = (const float*)d_in[7];
    const float* bB1 = (const float*)d_in[8];
    const float* WB2 = (const float*)d_in[9];
    const float* bB2 = (const float*)d_in[10];
    const float* WD1 = (const float*)d_in[11];
    const float* bD1 = (const float*)d_in[12];
    const float* WD2 = (const float*)d_in[13];
    const float* bD2 = (const float*)d_in[14];
    const float* WE1 = (const float*)d_in[15];
    const float* bE1 = (const float*)d_in[16];
    const float* WE2 = (const float*)d_in[17];
    const float* bE2 = (const float*)d_in[18];
    float* out = (float*)d_out;

    float *Asz, *t64, *bxp, *sn;
    __nv_bfloat16 *Ahi, *Alo, *Yhi, *Ylo, *SZhi, *SZlo;
    __nv_bfloat16 *W1h, *W1l, *W2h, *W2l;
    cudaGetSymbolAddress((void**)&Asz,  g_Asz);
    cudaGetSymbolAddress((void**)&t64,  g_t64);
    cudaGetSymbolAddress((void**)&bxp,  g_bx);
    cudaGetSymbolAddress((void**)&sn,   g_sn);
    cudaGetSymbolAddress((void**)&Ahi,  g_Ahi);
    cudaGetSymbolAddress((void**)&Alo,  g_Alo);
    cudaGetSymbolAddress((void**)&Yhi,  g_Yhi);
    cudaGetSymbolAddress((void**)&Ylo,  g_Ylo);
    cudaGetSymbolAddress((void**)&SZhi, g_SZhi);
    cudaGetSymbolAddress((void**)&SZlo, g_SZlo);
    cudaGetSymbolAddress((void**)&W1h,  g_W1h);
    cudaGetSymbolAddress((void**)&W1l,  g_W1l);
    cudaGetSymbolAddress((void**)&W2h,  g_W2h);
    cudaGetSymbolAddress((void**)&W2l,  g_W2l);

    int smCount = 148;
    cudaDeviceGetAttribute(&smCount, cudaDevAttrMultiProcessorCount, 0);
    const int G = 2 * smCount;

    cudaFuncSetAttribute(tgemm_persist, cudaFuncAttributeMaxDynamicSharedMemorySize,
                         tg::SMEM_TOTAL);
    cudaFuncSetAttribute(fmlp, cudaFuncAttributeMaxDynamicSharedMemorySize,
                         fm::SMEM_TOTAL);

    auto w1h = [&](int i) { return W1h + (long)i * 128 * 64; };
    auto w1l = [&](int i) { return W1l + (long)i * 128 * 64; };
    auto w2h = [&](int i) { return W2h + (long)i * 64 * 128; };
    auto w2l = [&](int i) { return W2l + (long)i * 64 * 128; };

    const dim3 blk(256);
    const dim3 gF((unsigned)(ROWS / 128), 1, 1);
    const dim3 tblk(32, 8, 1);
    const dim3 gTr64(N / 32, (BATCH * 64) / 32, 1);

    const long nT64  = ROWS * 64;
    const long nAsz  = ROWS * 128;
    const unsigned zT = (unsigned)((nT64 / 4 + 255) / 256);
    const unsigned zA = (unsigned)((nAsz / 4 + 255) / 256);

    float* sOut = out + ROWS * 64;   // final s destination

    // --- one-time prep ---
    {
        const long n4 = ((long)N * N) / 4;
        split_A_kernel<<<(unsigned)((n4 + 255) / 256), blk>>>(A);
    }
    prep_w_kernel<<<64, blk>>>(WA1, WA2, w1h(0), w1l(0), w2h(0), w2l(0));
    prep_w_kernel<<<64, blk>>>(WB1, WB2, w1h(1), w1l(1), w2h(1), w2l(1));
    prep_w_kernel<<<64, blk>>>(WD1, WD2, w1h(2), w1l(2), w2h(2), w2l(2));
    prep_w_kernel<<<64, blk>>>(WE1, WE2, w1h(3), w1l(3), w2h(3), w2l(3));
    zero_buf_kernel<<<zT, blk>>>(t64, nT64);    // prologue only
    zero_buf_kernel<<<zA, blk>>>(Asz, nAsz);    // prologue only

    // --- t64 = A @ x_c ---
    split_transpose_kernel<<<gTr64, tblk>>>(x_c, Yhi, Ylo);
    tgemm_persist<<<G, blk, tg::SMEM_TOTAL>>>(Ahi, Alo, Yhi, Ylo, t64, 6, 2, G);
    // --- bx = mlpB(t64) ---
    fmlp<<<gF, blk, fm::SMEM_TOTAL>>>(t64, 64, w1h(1), w1l(1), bB1,
                                      w2h(1), w2l(1), bB2,
                                      nullptr, bxp, nullptr, nullptr, nullptr, 0,
                                      nullptr, 0);

    for (int it = 0; it < ITERS; it++) {
        if (it > 0) {
            // Asz was zeroed by previous iteration's mode-3 fmlp
            tgemm_persist<<<G, blk, tg::SMEM_TOTAL>>>(Ahi, Alo, SZhi, SZlo, Asz, 7, 4, G);
        }
        // y = mlpA(Asz[:, :64]) + bx -> Y; also zeroes t64 (consumed by prev
        // mode-2 / bx read, rewritten by the tgemm right after this kernel).
        fmlp<<<gF, blk, fm::SMEM_TOTAL>>>(Asz, 128, w1h(0), w1l(0), bA1,
                                          w2h(0), w2l(0), bA2,
                                          bxp, nullptr, Yhi, Ylo, nullptr, 1,
                                          t64, 64);
        // t64 = A @ y (accumulates into just-zeroed t64)
        tgemm_persist<<<G, blk, tg::SMEM_TOTAL>>>(Ahi, Alo, Yhi, Ylo, t64, 6, 2, G);
        // sn = mlpD(t64)
        fmlp<<<gF, blk, fm::SMEM_TOTAL>>>(t64, 64, w1h(2), w1l(2), bD1,
                                          w2h(2), w2l(2), bD2,
                                          nullptr, sn, nullptr, nullptr, nullptr, 2,
                                          nullptr, 0);
        // s = sn + mlpE(Asz[:, 64:]); z = soft(s) -> SZ; zeroes Asz for next
        // iteration's tgemm. Last iteration writes s straight into out.
        float* sDst = (it == ITERS - 1) ? sOut : sn;
        fmlp<<<gF, blk, fm::SMEM_TOTAL>>>(Asz + 64, 128, w1h(3), w1l(3), bE1,
                                          w2h(3), w2l(3), bE2,
                                          sn, sDst, SZhi, SZlo, alpha, 3,
                                          Asz, 128);
    }

    // --- out[:R*64] = mlpD(s) ; s already at out[R*64:] ---
    fmlp<<<gF, blk, fm::SMEM_TOTAL>>>(sOut, 64, w1h(2), w1l(2), bD1,
                                      w2h(2), w2l(2), bD2,
                                      nullptr, out, nullptr, nullptr, nullptr, 4,
                                      nullptr, 0);
}

// round 15
// speedup vs baseline: 1.6040x; 1.0171x over previous
#include <cuda_runtime.h>
#include <cuda_bf16.h>
#include <cstdint>

// ============================================================================
// GUSC1 ISTA-net round 15: fmlp smem shrunk to 96KB (W1/W2 time-multiplexed
// in one 32KB region, W2 cp.async overlapped with H store) -> 2 CTAs/SM.
// GEMM path unchanged (R13/R14 persistent tgemm).
// ============================================================================

namespace cfg {
constexpr int  BATCH = 4;
constexpr int  N     = 8192;
constexpr int  ITERS = 8;
constexpr long ROWS  = (long)BATCH * N;   // 32768
}

// ---------------------------------------------------------------------------
// Scratch (device globals)
// ---------------------------------------------------------------------------
__device__ float g_Asz [cfg::BATCH * cfg::N * 128];
__device__ float g_t64 [cfg::BATCH * cfg::N * 64];
__device__ float g_bx  [cfg::BATCH * cfg::N * 64];
__device__ float g_sn  [cfg::BATCH * cfg::N * 64];

__device__ __nv_bfloat16 g_Ahi[(long)cfg::N * cfg::N];
__device__ __nv_bfloat16 g_Alo[(long)cfg::N * cfg::N];
__device__ __nv_bfloat16 g_Yhi [256L * cfg::N];
__device__ __nv_bfloat16 g_Ylo [256L * cfg::N];
__device__ __nv_bfloat16 g_SZhi[512L * cfg::N];
__device__ __nv_bfloat16 g_SZlo[512L * cfg::N];

__device__ __nv_bfloat16 g_W1h[4][128 * 64];
__device__ __nv_bfloat16 g_W1l[4][128 * 64];
__device__ __nv_bfloat16 g_W2h[4][64 * 128];
__device__ __nv_bfloat16 g_W2l[4][64 * 128];

// ---------------------------------------------------------------------------
// helpers
// ---------------------------------------------------------------------------
__device__ __forceinline__ uint32_t smem_to_u32(const void* p) {
    uint32_t a;
    asm("{ .reg .u64 t; cvta.to.shared.u64 t, %1; cvt.u32.u64 %0, t; }"
        : "=r"(a) : "l"(p));
    return a;
}
__device__ __forceinline__ void cp_async16(uint32_t dst, const void* src) {
    asm volatile("cp.async.cg.shared.global [%0], [%1], 16;" :: "r"(dst), "l"(src));
}
__device__ __forceinline__ void cp_async_commit() {
    asm volatile("cp.async.commit_group;");
}
template <int NWAIT>
__device__ __forceinline__ void cp_async_wait() {
    asm volatile("cp.async.wait_group %0;" :: "n"(NWAIT));
}
__device__ __forceinline__ void ldsm_x4(uint32_t& r0, uint32_t& r1,
                                        uint32_t& r2, uint32_t& r3, uint32_t addr) {
    asm volatile("ldmatrix.sync.aligned.m8n8.x4.shared.b16 {%0,%1,%2,%3}, [%4];"
                 : "=r"(r0), "=r"(r1), "=r"(r2), "=r"(r3) : "r"(addr));
}
__device__ __forceinline__ void mma16816(float& c0, float& c1, float& c2, float& c3,
                                         uint32_t a0, uint32_t a1, uint32_t a2, uint32_t a3,
                                         uint32_t b0, uint32_t b1) {
    asm volatile("mma.sync.aligned.m16n8k16.row.col.f32.bf16.bf16.f32 "
                 "{%0,%1,%2,%3}, {%4,%5,%6,%7}, {%8,%9}, {%0,%1,%2,%3};"
                 : "+f"(c0), "+f"(c1), "+f"(c2), "+f"(c3)
                 : "r"(a0), "r"(a1), "r"(a2), "r"(a3), "r"(b0), "r"(b1));
}
__device__ __forceinline__ uint32_t pack_bf16x2(float lo, float hi) {
    __nv_bfloat162 p = __floats2bfloat162_rn(lo, hi);
    return *reinterpret_cast<uint32_t*>(&p);
}
__device__ __forceinline__ uint32_t swz(int row, int x) {
    return (uint32_t)(row * 128 + (x ^ ((row & 7) << 4)));
}
__device__ __forceinline__ uint32_t swzH(int row, int x) {
    return (uint32_t)(row * 256 + (x ^ ((row & 7) << 4)));
}

// ---------------------------------------------------------------------------
// Persistent split-bf16 HMMA GEMM (unchanged from R13/R14).
// ---------------------------------------------------------------------------
namespace tg {
constexpr int K   = 8192;
constexpr int KT  = 64;
constexpr uint32_t SZ_A = 64 * 128;
constexpr uint32_t SZ_B = 128 * 128;
constexpr uint32_t STG  = 2 * SZ_A + 2 * SZ_B;   // 49152
constexpr uint32_t SMEM_TOTAL = 2 * STG;         // 98304
}

__global__ __launch_bounds__(256, 2) void tgemm_persist(
    const __nv_bfloat16* __restrict__ Ahi, const __nv_bfloat16* __restrict__ Alo,
    const __nv_bfloat16* __restrict__ Bhi, const __nv_bfloat16* __restrict__ Blo,
    float* __restrict__ out, int cbShift, int nbN, int G)
{
    using namespace tg;
    extern __shared__ char smem[];
    const uint32_t sb  = smem_to_u32(smem);
    const int tid  = threadIdx.x;
    const int lane = tid & 31;
    const int wid  = tid >> 5;
    const int wm   = wid >> 2;
    const int wn   = wid & 3;

    const int U = nbN * 128 * 128;
    const int uStart = (int)(((long)U * blockIdx.x) / G);
    const int uEnd   = (int)(((long)U * (blockIdx.x + 1)) / G);
    if (uStart >= uEnd) return;

    const int c0r = tid >> 3;
    const int c0s = tid & 7;

    float acc[2][4][4];
#pragma unroll
    for (int i = 0; i < 2; i++)
#pragma unroll
        for (int j = 0; j < 4; j++)
#pragma unroll
            for (int q2 = 0; q2 < 4; q2++) acc[i][j][q2] = 0.f;

    const int q  = lane >> 3;
    const int r8 = lane & 7;
    const int a_row_off = wm * 32 + r8 + (q & 1) * 8;
    const int a_k_off   = (q >> 1) * 16;
    const int b_row_off = wn * 32 + r8 + (q >> 1) * 8;
    const int b_k_off   = (q & 1) * 16;

#define LOAD_UNIT(ST, UU)                                                      \
    do {                                                                       \
        const int tile_ = (UU) >> 7;                                           \
        const int m0_   = (tile_ & 127) * 64;                                  \
        const int n0_   = (tile_ >> 7) * 128;                                  \
        const int k0_   = ((UU) & 127) * KT;                                   \
        const uint32_t base_ = sb + (uint32_t)(ST) * STG;                      \
        const uint32_t oA0_ = swz(c0r,      c0s * 16);                         \
        const uint32_t oA1_ = swz(c0r + 32, c0s * 16);                         \
        const int ga0_ = (m0_ + c0r)      * K + k0_ + c0s * 8;                 \
        const int ga1_ = (m0_ + c0r + 32) * K + k0_ + c0s * 8;                 \
        cp_async16(base_ + oA0_,        Ahi + ga0_);                           \
        cp_async16(base_ + oA1_,        Ahi + ga1_);                           \
        cp_async16(base_ + SZ_A + oA0_, Alo + ga0_);                           \
        cp_async16(base_ + SZ_A + oA1_, Alo + ga1_);                           \
        const uint32_t bB_ = base_ + 2 * SZ_A;                                 \
        _Pragma("unroll")                                                      \
        for (int rr_ = 0; rr_ < 4; rr_++) {                                    \
            const int brow_ = c0r + rr_ * 32;                                  \
            const uint32_t oB_ = swz(brow_, c0s * 16);                         \
            const int gb_ = (n0_ + brow_) * K + k0_ + c0s * 8;                 \
            cp_async16(bB_ + oB_,        Bhi + gb_);                           \
            cp_async16(bB_ + SZ_B + oB_, Blo + gb_);                           \
        }                                                                      \
        cp_async_commit();                                                     \
    } while (0)

    LOAD_UNIT(uStart & 1, uStart);

    for (int u = uStart; u < uEnd; u++) {
        if (u + 1 < uEnd) {
            LOAD_UNIT((u + 1) & 1, u + 1);
            cp_async_wait<1>();
        } else {
            cp_async_wait<0>();
        }
        __syncthreads();

        const uint32_t base = sb + (uint32_t)(u & 1) * STG;
        const uint32_t aHB = base;
        const uint32_t aLB = base + SZ_A;
        const uint32_t bHB = base + 2 * SZ_A;
        const uint32_t bLB = base + 2 * SZ_A + SZ_B;

#pragma unroll
        for (int s = 0; s < 4; s++) {
            const int kb = s * 32;
            uint32_t ah[2][4], al[2][4], bh[2][4], bl[2][4];
#pragma unroll
            for (int mi = 0; mi < 2; mi++) {
                const uint32_t ad = swz(a_row_off + mi * 16, kb + a_k_off);
                ldsm_x4(ah[mi][0], ah[mi][1], ah[mi][2], ah[mi][3], aHB + ad);
                ldsm_x4(al[mi][0], al[mi][1], al[mi][2], al[mi][3], aLB + ad);
            }
#pragma unroll
            for (int ni = 0; ni < 2; ni++) {
                const uint32_t bd = swz(b_row_off + ni * 16, kb + b_k_off);
                ldsm_x4(bh[ni][0], bh[ni][1], bh[ni][2], bh[ni][3], bHB + bd);
                ldsm_x4(bl[ni][0], bl[ni][1], bl[ni][2], bl[ni][3], bLB + bd);
            }
#pragma unroll
            for (int mi = 0; mi < 2; mi++)
#pragma unroll
                for (int nj = 0; nj < 4; nj++) {
                    const int g = nj >> 1, h = (nj & 1) * 2;
                    float* c = acc[mi][nj];
                    mma16816(c[0], c[1], c[2], c[3],
                             ah[mi][0], ah[mi][1], ah[mi][2], ah[mi][3],
                             bh[g][h], bh[g][h + 1]);
                }
#pragma unroll
            for (int mi = 0; mi < 2; mi++)
#pragma unroll
                for (int nj = 0; nj < 4; nj++) {
                    const int g = nj >> 1, h = (nj & 1) * 2;
                    float* c = acc[mi][nj];
                    mma16816(c[0], c[1], c[2], c[3],
                             al[mi][0], al[mi][1], al[mi][2], al[mi][3],
                             bh[g][h], bh[g][h + 1]);
                }
#pragma unroll
            for (int mi = 0; mi < 2; mi++)
#pragma unroll
                for (int nj = 0; nj < 4; nj++) {
                    const int g = nj >> 1, h = (nj & 1) * 2;
                    float* c = acc[mi][nj];
                    mma16816(c[0], c[1], c[2], c[3],
                             ah[mi][0], ah[mi][1], ah[mi][2], ah[mi][3],
                             bl[g][h], bl[g][h + 1]);
                }
        }

        if (u + 1 == uEnd || ((u + 1) & 127) == 0) {
            const int tile = u >> 7;
            const int m0 = (tile & 127) * 64;
            const int n0 = (tile >> 7) * 128;
            const int CB = 1 << cbShift;
#pragma unroll
            for (int mi = 0; mi < 2; mi++) {
                const int row = m0 + wm * 32 + mi * 16 + (lane >> 2);
#pragma unroll
                for (int nj = 0; nj < 4; nj++) {
                    const int g = n0 + wn * 32 + nj * 8 + 2 * (lane & 3);
                    const int b = g >> cbShift;
                    const int c = g & (CB - 1);
                    const int base0 = (b * 8192 + row) * CB + c;
                    atomicAdd(out + base0,              acc[mi][nj][0]);
                    atomicAdd(out + base0 + 1,          acc[mi][nj][1]);
                    atomicAdd(out + base0 + 8 * CB,     acc[mi][nj][2]);
                    atomicAdd(out + base0 + 8 * CB + 1, acc[mi][nj][3]);
                    acc[mi][nj][0] = acc[mi][nj][1] = 0.f;
                    acc[mi][nj][2] = acc[mi][nj][3] = 0.f;
                }
            }
        }
        __syncthreads();
    }
#undef LOAD_UNIT
}

// ---------------------------------------------------------------------------
// Fused 2-layer MLP, 96KB smem (W region time-multiplexed W1 -> W2), 2 CTA/SM.
// ---------------------------------------------------------------------------
namespace fm {
constexpr uint32_t O_W1H = 0;        // phase 1: W1 hi/lo (2 x 16KB)
constexpr uint32_t O_W1L = 16384;
constexpr uint32_t O_W2H = 0;        // phase 2: W2 hi/lo (2 x 16KB), same region
constexpr uint32_t O_W2L = 16384;
constexpr uint32_t O_XF  = 32768;    // 32KB fp32 X
constexpr uint32_t O_XH  = 65536;    // 16KB
constexpr uint32_t O_XL  = 81920;    // 16KB
constexpr uint32_t O_HH  = 32768;    // 32KB (overwrites XF)
constexpr uint32_t O_HL  = 65536;    // 32KB (overwrites XH/XL)
constexpr uint32_t O_T   = 32768;    // up to 64KB (overwrites H)
constexpr uint32_t SMEM_TOTAL = 98304;
}

__global__ __launch_bounds__(256, 2) void fmlp(
    const float* __restrict__ X, int ldx,
    const __nv_bfloat16* __restrict__ W1h, const __nv_bfloat16* __restrict__ W1l,
    const float* __restrict__ b1,
    const __nv_bfloat16* __restrict__ W2h, const __nv_bfloat16* __restrict__ W2l,
    const float* __restrict__ b2,
    const float* __restrict__ add,
    float* __restrict__ outF,
    __nv_bfloat16* __restrict__ outKh, __nv_bfloat16* __restrict__ outKl,
    const float* __restrict__ alphaPtr, int mode,
    float* __restrict__ zbuf, int zcols)
{
    using namespace fm;
    extern __shared__ char smem[];
    const uint32_t sb = smem_to_u32(smem);
    const int tid  = threadIdx.x;
    const int lane = tid & 31;
    const int wid  = tid >> 5;
    const long m0  = (long)blockIdx.x * 128;

    // ---- phase-1 loads: W1 hi/lo + X fp32 ----
    {
#pragma unroll
        for (int j = 0; j < 4; j++) {
            const int idx = tid + j * 256;
            const int row = idx >> 3, seg = idx & 7;
            const uint32_t o = swz(row, seg * 16);
            cp_async16(sb + O_W1H + o, W1h + row * 64 + seg * 8);
            cp_async16(sb + O_W1L + o, W1l + row * 64 + seg * 8);
        }
#pragma unroll
        for (int j = 0; j < 8; j++) {
            const int idx = tid + j * 256;
            const int row = idx >> 4, seg = idx & 15;
            cp_async16(sb + O_XF + row * 256 + seg * 16,
                       X + (m0 + row) * (long)ldx + seg * 4);
        }
        cp_async_commit();
        cp_async_wait<0>();
        __syncthreads();
    }

#pragma unroll
    for (int j = 0; j < 16; j++) {
        const int p = tid + j * 256;
        const int row = p >> 5, kp = p & 31;
        const float2 v = *reinterpret_cast<const float2*>(smem + O_XF + row * 256 + kp * 8);
        const __nv_bfloat16 h0 = __float2bfloat16(v.x);
        const __nv_bfloat16 h1 = __float2bfloat16(v.y);
        const float l0 = v.x - __bfloat162float(h0);
        const float l1 = v.y - __bfloat162float(h1);
        const uint32_t oo = swz(row, kp * 4);
        *reinterpret_cast<uint32_t*>(smem + O_XH + oo) =
            ((uint32_t)*reinterpret_cast<const uint16_t*>(&h1) << 16) |
             (uint32_t)*reinterpret_cast<const uint16_t*>(&h0);
        *reinterpret_cast<uint32_t*>(smem + O_XL + oo) = pack_bf16x2(l0, l1);
    }
    __syncthreads();

    // fused zeroing of the CTA's rows in zbuf
    if (zbuf != nullptr) {
        float4* zp = reinterpret_cast<float4*>(zbuf + m0 * zcols);
        const int tot = 128 * zcols / 4;
        const float4 z4 = make_float4(0.f, 0.f, 0.f, 0.f);
        for (int i = tid; i < tot; i += 256) zp[i] = z4;
    }

    const int q  = lane >> 3;
    const int r8 = lane & 7;

    // ---- GEMM1: warps 2m x 4n, warp tile 64x32; A frags loaded per-mi ----
    float acc1[4][4][4];
#pragma unroll
    for (int i = 0; i < 4; i++)
#pragma unroll
        for (int j = 0; j < 4; j++)
#pragma unroll
            for (int k = 0; k < 4; k++) acc1[i][j][k] = 0.f;
    {
        const int wm1 = wid >> 2, wn1 = wid & 3;
        const int ar = wm1 * 64 + r8 + (q & 1) * 8;
        const int ax = (q >> 1) * 16;
        const int br = wn1 * 32 + r8 + (q >> 1) * 8;
        const int bx = (q & 1) * 16;
#pragma unroll
        for (int s = 0; s < 4; s++) {
            const int kx = s * 32;
            uint32_t bh[2][4], bl[2][4];
#pragma unroll
            for (int ni = 0; ni < 2; ni++) {
                const uint32_t bd = swz(br + ni * 16, kx + bx);
                ldsm_x4(bh[ni][0], bh[ni][1], bh[ni][2], bh[ni][3], sb + O_W1H + bd);
                ldsm_x4(bl[ni][0], bl[ni][1], bl[ni][2], bl[ni][3], sb + O_W1L + bd);
            }
#pragma unroll
            for (int mi = 0; mi < 4; mi++) {
                uint32_t ah[4], al[4];
                const uint32_t ad = swz(ar + mi * 16, kx + ax);
                ldsm_x4(ah[0], ah[1], ah[2], ah[3], sb + O_XH + ad);
                ldsm_x4(al[0], al[1], al[2], al[3], sb + O_XL + ad);
#pragma unroll
                for (int nj = 0; nj < 4; nj++) {
                    const int g = nj >> 1, h = (nj & 1) * 2;
                    float* c = acc1[mi][nj];
                    mma16816(c[0], c[1], c[2], c[3],
                             ah[0], ah[1], ah[2], ah[3], bh[g][h], bh[g][h + 1]);
                    mma16816(c[0], c[1], c[2], c[3],
                             al[0], al[1], al[2], al[3], bh[g][h], bh[g][h + 1]);
                    mma16816(c[0], c[1], c[2], c[3],
                             ah[0], ah[1], ah[2], ah[3], bl[g][h], bl[g][h + 1]);
                }
            }
        }
    }
    __syncthreads();   // W1, XH/XL fully consumed

    // ---- issue W2 loads into the W region (W1 dead), overlapped with H store
    {
#pragma unroll
        for (int j = 0; j < 4; j++) {
            const int idx = tid + j * 256;
            const int row = idx >> 4, seg = idx & 15;
            const uint32_t o = swzH(row, seg * 16);
            cp_async16(sb + O_W2H + o, W2h + row * 128 + seg * 8);
            cp_async16(sb + O_W2L + o, W2l + row * 128 + seg * 8);
        }
        cp_async_commit();
    }

    // ---- +b1, relu, split, store H ----
    {
        const int wm1 = wid >> 2, wn1 = wid & 3;
#pragma unroll
        for (int mi = 0; mi < 4; mi++) {
            const int row0 = wm1 * 64 + mi * 16 + (lane >> 2);
#pragma unroll
            for (int nj = 0; nj < 4; nj++) {
                const int n = wn1 * 32 + nj * 8 + 2 * (lane & 3);
                const float bb0 = __ldg(b1 + n);
                const float bb1 = __ldg(b1 + n + 1);
                float v0 = fmaxf(acc1[mi][nj][0] + bb0, 0.f);
                float v1 = fmaxf(acc1[mi][nj][1] + bb1, 0.f);
                float v2 = fmaxf(acc1[mi][nj][2] + bb0, 0.f);
                float v3 = fmaxf(acc1[mi][nj][3] + bb1, 0.f);
                const __nv_bfloat16 h0 = __float2bfloat16(v0);
                const __nv_bfloat16 h1 = __float2bfloat16(v1);
                const __nv_bfloat16 h2 = __float2bfloat16(v2);
                const __nv_bfloat16 h3 = __float2bfloat16(v3);
                const uint32_t o0 = swzH(row0,     n * 2);
                const uint32_t o1 = swzH(row0 + 8, n * 2);
                *reinterpret_cast<uint32_t*>(smem + O_HH + o0) =
                    ((uint32_t)*reinterpret_cast<const uint16_t*>(&h1) << 16) |
                     (uint32_t)*reinterpret_cast<const uint16_t*>(&h0);
                *reinterpret_cast<uint32_t*>(smem + O_HH + o1) =
                    ((uint32_t)*reinterpret_cast<const uint16_t*>(&h3) << 16) |
                     (uint32_t)*reinterpret_cast<const uint16_t*>(&h2);
                *reinterpret_cast<uint32_t*>(smem + O_HL + o0) =
                    pack_bf16x2(v0 - __bfloat162float(h0), v1 - __bfloat162float(h1));
                *reinterpret_cast<uint32_t*>(smem + O_HL + o1) =
                    pack_bf16x2(v2 - __bfloat162float(h2), v3 - __bfloat162float(h3));
            }
        }
    }
    cp_async_wait<0>();
    __syncthreads();

    // ---- GEMM2: warps 4m x 2n, warp tile 32x32 ----
    float acc2[2][4][4];
#pragma unroll
    for (int i = 0; i < 2; i++)
#pragma unroll
        for (int j = 0; j < 4; j++)
#pragma unroll
            for (int k = 0; k < 4; k++) acc2[i][j][k] = 0.f;
    const int wm2 = wid >> 1, wn2 = wid & 1;
    {
        const int ar = wm2 * 32 + r8 + (q & 1) * 8;
        const int ax = (q >> 1) * 16;
        const int br = wn2 * 32 + r8 + (q >> 1) * 8;
        const int bx = (q & 1) * 16;
#pragma unroll
        for (int s = 0; s < 8; s++) {
            const int kx = s * 32;
            uint32_t ah[2][4], al[2][4], bh[2][4], bl[2][4];
#pragma unroll
            for (int mi = 0; mi < 2; mi++) {
                const uint32_t ad = swzH(ar + mi * 16, kx + ax);
                ldsm_x4(ah[mi][0], ah[mi][1], ah[mi][2], ah[mi][3], sb + O_HH + ad);
                ldsm_x4(al[mi][0], al[mi][1], al[mi][2], al[mi][3], sb + O_HL + ad);
            }
#pragma unroll
            for (int ni = 0; ni < 2; ni++) {
                const uint32_t bd = swzH(br + ni * 16, kx + bx);
                ldsm_x4(bh[ni][0], bh[ni][1], bh[ni][2], bh[ni][3], sb + O_W2H + bd);
                ldsm_x4(bl[ni][0], bl[ni][1], bl[ni][2], bl[ni][3], sb + O_W2L + bd);
            }
#pragma unroll
            for (int mi = 0; mi < 2; mi++)
#pragma unroll
                for (int nj = 0; nj < 4; nj++) {
                    const int g = nj >> 1, h = (nj & 1) * 2;
                    float* c = acc2[mi][nj];
                    mma16816(c[0], c[1], c[2], c[3],
                             ah[mi][0], ah[mi][1], ah[mi][2], ah[mi][3],
                             bh[g][h], bh[g][h + 1]);
                    mma16816(c[0], c[1], c[2], c[3],
                             al[mi][0], al[mi][1], al[mi][2], al[mi][3],
                             bh[g][h], bh[g][h + 1]);
                    mma16816(c[0], c[1], c[2], c[3],
                             ah[mi][0], ah[mi][1], ah[mi][2], ah[mi][3],
                             bl[g][h], bl[g][h + 1]);
                }
        }
    }
    __syncthreads();   // H dead; region becomes T

    const float alpha = (mode == 3) ? __ldg(alphaPtr) : 0.f;
    const uint32_t tSz = (mode == 3) ? 32768u : 16384u;
#pragma unroll
    for (int mi = 0; mi < 2; mi++) {
        const int  rl0 = wm2 * 32 + mi * 16 + (lane >> 2);
#pragma unroll
        for (int nj = 0; nj < 4; nj++) {
            const int c = wn2 * 32 + nj * 8 + 2 * (lane & 3);
            const float bb0 = __ldg(b2 + c);
            const float bb1 = __ldg(b2 + c + 1);
            float v[4];
            v[0] = acc2[mi][nj][0] + bb0;
            v[1] = acc2[mi][nj][1] + bb1;
            v[2] = acc2[mi][nj][2] + bb0;
            v[3] = acc2[mi][nj][3] + bb1;
            if (add != nullptr) {
                const float2 a0 = *reinterpret_cast<const float2*>(add + (m0 + rl0) * 64 + c);
                const float2 a1 = *reinterpret_cast<const float2*>(add + (m0 + rl0 + 8) * 64 + c);
                v[0] += a0.x; v[1] += a0.y; v[2] += a1.x; v[3] += a1.y;
            }
            if (outF != nullptr) {
                *reinterpret_cast<float2*>(outF + (m0 + rl0) * 64 + c)     = make_float2(v[0], v[1]);
                *reinterpret_cast<float2*>(outF + (m0 + rl0 + 8) * 64 + c) = make_float2(v[2], v[3]);
            }
            if (mode == 1 || mode == 3) {
#pragma unroll
                for (int e = 0; e < 4; e++) {
                    const int rl = rl0 + (e >> 1) * 8;
                    const int cc = c + (e & 1);
                    const float s = v[e];
                    const __nv_bfloat16 hi = __float2bfloat16(s);
                    *reinterpret_cast<__nv_bfloat16*>(smem + O_T + cc * 256 + rl * 2) = hi;
                    *reinterpret_cast<__nv_bfloat16*>(smem + O_T + tSz + cc * 256 + rl * 2) =
                        __float2bfloat16(s - __bfloat162float(hi));
                    if (mode == 3) {
                        const float z = (s > alpha) ? (s - alpha)
                                                    : ((s < -alpha) ? (s + alpha) : 0.f);
                        const __nv_bfloat16 zh = __float2bfloat16(z);
                        *reinterpret_cast<__nv_bfloat16*>(smem + O_T + (64 + cc) * 256 + rl * 2) = zh;
                        *reinterpret_cast<__nv_bfloat16*>(smem + O_T + tSz + (64 + cc) * 256 + rl * 2) =
                            __float2bfloat16(z - __bfloat162float(zh));
                    }
                }
            }
        }
    }

    if (mode == 1 || mode == 3) {
        __syncthreads();
        const int CB = (mode == 3) ? 128 : 64;
        const long bb = m0 >> 13;
        const long k0 = m0 & 8191;
        const int total = CB * 16 * 2;
        for (int idx = tid; idx < total; idx += 256) {
            const int arr = idx >= CB * 16;
            const int rem = arr ? idx - CB * 16 : idx;
            const int j   = rem >> 4;
            const int s16 = rem & 15;
            const uint4 val = *reinterpret_cast<const uint4*>(
                smem + O_T + (uint32_t)arr * tSz + j * 256 + s16 * 16);
            __nv_bfloat16* dst = (arr ? outKl : outKh) +
                ((long)(bb * CB + j)) * 8192 + k0 + s16 * 8;
            *reinterpret_cast<uint4*>(dst) = val;
        }
    }
}

// ---------------------------------------------------------------------------
__global__ __launch_bounds__(256) void prep_w_kernel(
    const float* __restrict__ W1, const float* __restrict__ W2,
    __nv_bfloat16* __restrict__ w1h, __nv_bfloat16* __restrict__ w1l,
    __nv_bfloat16* __restrict__ w2h, __nv_bfloat16* __restrict__ w2l)
{
    const int id = blockIdx.x * 256 + threadIdx.x;
    if (id < 8192) {
        const int n = id >> 6, k = id & 63;
        const float v = W1[k * 128 + n];
        const __nv_bfloat16 h = __float2bfloat16(v);
        w1h[id] = h;
        w1l[id] = __float2bfloat16(v - __bfloat162float(h));
    } else if (id < 16384) {
        const int i2 = id - 8192;
        const int n = i2 >> 7, k = i2 & 127;
        const float v = W2[k * 64 + n];
        const __nv_bfloat16 h = __float2bfloat16(v);
        w2h[i2] = h;
        w2l[i2] = __float2bfloat16(v - __bfloat162float(h));
    }
}

__global__ __launch_bounds__(256) void split_A_kernel(const float* __restrict__ A)
{
    const long n = (long)cfg::N * cfg::N;
    long idx = ((long)blockIdx.x * blockDim.x + threadIdx.x) * 4;
    if (idx >= n) return;
    float4 v = *reinterpret_cast<const float4*>(A + idx);
    float f[4] = {v.x, v.y, v.z, v.w};
#pragma unroll
    for (int q = 0; q < 4; q++) {
        __nv_bfloat16 hi = __float2bfloat16(f[q]);
        g_Ahi[idx + q] = hi;
        g_Alo[idx + q] = __float2bfloat16(f[q] - __bfloat162float(hi));
    }
}

__global__ __launch_bounds__(256) void split_transpose_kernel(
    const float* __restrict__ X,
    __nv_bfloat16* __restrict__ oh, __nv_bfloat16* __restrict__ ol)
{
    __shared__ float tile[32][33];
    const int k0 = blockIdx.x * 32;
    const int j0 = blockIdx.y * 32;
    const int b  = j0 / 64;
    const int c0 = j0 % 64;
    const int tx = threadIdx.x, ty = threadIdx.y;

    for (int r = ty; r < 32; r += 8)
        tile[r][tx] = X[((long)b * cfg::N + k0 + r) * 64 + c0 + tx];
    __syncthreads();
    for (int r = ty; r < 32; r += 8) {
        const float v = tile[tx][r];
        const __nv_bfloat16 hi = __float2bfloat16(v);
        const long o = (long)(j0 + r) * cfg::N + k0 + tx;
        oh[o] = hi;
        ol[o] = __float2bfloat16(v - __bfloat162float(hi));
    }
}

__global__ __launch_bounds__(256) void zero_buf_kernel(float* __restrict__ p, long n)
{
    long idx = ((long)blockIdx.x * blockDim.x + threadIdx.x) * 4;
    if (idx < n) *reinterpret_cast<float4*>(p + idx) = make_float4(0.f, 0.f, 0.f, 0.f);
}

// ============================================================================
extern "C" void kernel_launch(void* const* d_in, const int* in_sizes, int n_in,
                              void* d_out, int out_size)
{
    using namespace cfg;
    const float* x_c   = (const float*)d_in[0];
    const float* A     = (const float*)d_in[1];
    const float* alpha = (const float*)d_in[2];
    const float* WA1 = (const float*)d_in[3];
    const float* bA1 = (const float*)d_in[4];
    const float* WA2 = (const float*)d_in[5];
    const float* bA2 = (const float*)d_in[6];
    const float* WB1 = (const float*)d_in[7];
    const float* bB1 = (const float*)d_in[8];
    const float* WB2 = (const float*)d_in[9];
    const float* bB2 = (const float*)d_in[10];
    const float* WD1 = (const float*)d_in[11];
    const float* bD1 = (const float*)d_in[12];
    const float* WD2 = (const float*)d_in[13];
    const float* bD2 = (const float*)d_in[14];
    const float* WE1 = (const float*)d_in[15];
    const float* bE1 = (const float*)d_in[16];
    const float* WE2 = (const float*)d_in[17];
    const float* bE2 = (const float*)d_in[18];
    float* out = (float*)d_out;

    float *Asz, *t64, *bxp, *sn;
    __nv_bfloat16 *Ahi, *Alo, *Yhi, *Ylo, *SZhi, *SZlo;
    __nv_bfloat16 *W1h, *W1l, *W2h, *W2l;
    cudaGetSymbolAddress((void**)&Asz,  g_Asz);
    cudaGetSymbolAddress((void**)&t64,  g_t64);
    cudaGetSymbolAddress((void**)&bxp,  g_bx);
    cudaGetSymbolAddress((void**)&sn,   g_sn);
    cudaGetSymbolAddress((void**)&Ahi,  g_Ahi);
    cudaGetSymbolAddress((void**)&Alo,  g_Alo);
    cudaGetSymbolAddress((void**)&Yhi,  g_Yhi);
    cudaGetSymbolAddress((void**)&Ylo,  g_Ylo);
    cudaGetSymbolAddress((void**)&SZhi, g_SZhi);
    cudaGetSymbolAddress((void**)&SZlo, g_SZlo);
    cudaGetSymbolAddress((void**)&W1h,  g_W1h);
    cudaGetSymbolAddress((void**)&W1l,  g_W1l);
    cudaGetSymbolAddress((void**)&W2h,  g_W2h);
    cudaGetSymbolAddress((void**)&W2l,  g_W2l);

    int smCount = 148;
    cudaDeviceGetAttribute(&smCount, cudaDevAttrMultiProcessorCount, 0);
    const int G = 2 * smCount;

    cudaFuncSetAttribute(tgemm_persist, cudaFuncAttributeMaxDynamicSharedMemorySize,
                         tg::SMEM_TOTAL);
    cudaFuncSetAttribute(fmlp, cudaFuncAttributeMaxDynamicSharedMemorySize,
                         fm::SMEM_TOTAL);

    auto w1h = [&](int i) { return W1h + (long)i * 128 * 64; };
    auto w1l = [&](int i) { return W1l + (long)i * 128 * 64; };
    auto w2h = [&](int i) { return W2h + (long)i * 64 * 128; };
    auto w2l = [&](int i) { return W2l + (long)i * 64 * 128; };

    const dim3 blk(256);
    const dim3 gF((unsigned)(ROWS / 128), 1, 1);
    const dim3 tblk(32, 8, 1);
    const dim3 gTr64(N / 32, (BATCH * 64) / 32, 1);

    const long nT64  = ROWS * 64;
    const long nAsz  = ROWS * 128;
    const unsigned zT = (unsigned)((nT64 / 4 + 255) / 256);
    const unsigned zA = (unsigned)((nAsz / 4 + 255) / 256);

    float* sOut = out + ROWS * 64;

    // --- one-time prep ---
    {
        const long n4 = ((long)N * N) / 4;
        split_A_kernel<<<(unsigned)((n4 + 255) / 256), blk>>>(A);
    }
    prep_w_kernel<<<64, blk>>>(WA1, WA2, w1h(0), w1l(0), w2h(0), w2l(0));
    prep_w_kernel<<<64, blk>>>(WB1, WB2, w1h(1), w1l(1), w2h(1), w2l(1));
    prep_w_kernel<<<64, blk>>>(WD1, WD2, w1h(2), w1l(2), w2h(2), w2l(2));
    prep_w_kernel<<<64, blk>>>(WE1, WE2, w1h(3), w1l(3), w2h(3), w2l(3));
    zero_buf_kernel<<<zT, blk>>>(t64, nT64);
    zero_buf_kernel<<<zA, blk>>>(Asz, nAsz);

    // --- t64 = A @ x_c ---
    split_transpose_kernel<<<gTr64, tblk>>>(x_c, Yhi, Ylo);
    tgemm_persist<<<G, blk, tg::SMEM_TOTAL>>>(Ahi, Alo, Yhi, Ylo, t64, 6, 2, G);
    // --- bx = mlpB(t64) ---
    fmlp<<<gF, blk, fm::SMEM_TOTAL>>>(t64, 64, w1h(1), w1l(1), bB1,
                                      w2h(1), w2l(1), bB2,
                                      nullptr, bxp, nullptr, nullptr, nullptr, 0,
                                      nullptr, 0);

    for (int it = 0; it < ITERS; it++) {
        if (it > 0) {
            tgemm_persist<<<G, blk, tg::SMEM_TOTAL>>>(Ahi, Alo, SZhi, SZlo, Asz, 7, 4, G);
        }
        // y = mlpA(Asz[:, :64]) + bx -> Y; zeroes t64
        fmlp<<<gF, blk, fm::SMEM_TOTAL>>>(Asz, 128, w1h(0), w1l(0), bA1,
                                          w2h(0), w2l(0), bA2,
                                          bxp, nullptr, Yhi, Ylo, nullptr, 1,
                                          t64, 64);
        // t64 = A @ y
        tgemm_persist<<<G, blk, tg::SMEM_TOTAL>>>(Ahi, Alo, Yhi, Ylo, t64, 6, 2, G);
        // sn = mlpD(t64)
        fmlp<<<gF, blk, fm::SMEM_TOTAL>>>(t64, 64, w1h(2), w1l(2), bD1,
                                          w2h(2), w2l(2), bD2,
                                          nullptr, sn, nullptr, nullptr, nullptr, 2,
                                          nullptr, 0);
        // s = sn + mlpE(Asz[:, 64:]); z = soft(s) -> SZ; zeroes Asz
        float* sDst = (it == ITERS - 1) ? sOut : sn;
        fmlp<<<gF, blk, fm::SMEM_TOTAL>>>(Asz + 64, 128, w1h(3), w1l(3), bE1,
                                          w2h(3), w2l(3), bE2,
                                          sn, sDst, SZhi, SZlo, alpha, 3,
                                          Asz, 128);
    }

    // --- out[:R*64] = mlpD(s) ; s already at out[R*64:] ---
    fmlp<<<gF, blk, fm::SMEM_TOTAL>>>(sOut, 64, w1h(2), w1l(2), bD1,
                                      w2h(2), w2l(2), bD2,
                                      nullptr, out, nullptr, nullptr, nullptr, 4,
                                      nullptr, 0);
}

// round 16
// speedup vs baseline: 1.6216x; 1.0109x over previous
#include <cuda_runtime.h>
#include <cuda_bf16.h>
#include <cstdint>

// ============================================================================
// GUSC1 ISTA-net round 16: iteration restructured to 2 fmlp launches
// (AE dual-phase + D3), dead sn writes removed. GEMM unchanged (R13).
// ============================================================================

namespace cfg {
constexpr int  BATCH = 4;
constexpr int  N     = 8192;
constexpr int  ITERS = 8;
constexpr long ROWS  = (long)BATCH * N;   // 32768
}

// ---------------------------------------------------------------------------
// Scratch (device globals)
// ---------------------------------------------------------------------------
__device__ float g_Asz [cfg::BATCH * cfg::N * 128];
__device__ float g_t64 [cfg::BATCH * cfg::N * 64];
__device__ float g_bx  [cfg::BATCH * cfg::N * 64];
__device__ float g_e   [cfg::BATCH * cfg::N * 64];   // mlpE output

__device__ __nv_bfloat16 g_Ahi[(long)cfg::N * cfg::N];
__device__ __nv_bfloat16 g_Alo[(long)cfg::N * cfg::N];
__device__ __nv_bfloat16 g_Yhi [256L * cfg::N];
__device__ __nv_bfloat16 g_Ylo [256L * cfg::N];
__device__ __nv_bfloat16 g_SZhi[512L * cfg::N];
__device__ __nv_bfloat16 g_SZlo[512L * cfg::N];

__device__ __nv_bfloat16 g_W1h[4][128 * 64];
__device__ __nv_bfloat16 g_W1l[4][128 * 64];
__device__ __nv_bfloat16 g_W2h[4][64 * 128];
__device__ __nv_bfloat16 g_W2l[4][64 * 128];

// ---------------------------------------------------------------------------
// helpers
// ---------------------------------------------------------------------------
__device__ __forceinline__ uint32_t smem_to_u32(const void* p) {
    uint32_t a;
    asm("{ .reg .u64 t; cvta.to.shared.u64 t, %1; cvt.u32.u64 %0, t; }"
        : "=r"(a) : "l"(p));
    return a;
}
__device__ __forceinline__ void cp_async16(uint32_t dst, const void* src) {
    asm volatile("cp.async.cg.shared.global [%0], [%1], 16;" :: "r"(dst), "l"(src));
}
__device__ __forceinline__ void cp_async_commit() {
    asm volatile("cp.async.commit_group;");
}
template <int NWAIT>
__device__ __forceinline__ void cp_async_wait() {
    asm volatile("cp.async.wait_group %0;" :: "n"(NWAIT));
}
__device__ __forceinline__ void ldsm_x4(uint32_t& r0, uint32_t& r1,
                                        uint32_t& r2, uint32_t& r3, uint32_t addr) {
    asm volatile("ldmatrix.sync.aligned.m8n8.x4.shared.b16 {%0,%1,%2,%3}, [%4];"
                 : "=r"(r0), "=r"(r1), "=r"(r2), "=r"(r3) : "r"(addr));
}
__device__ __forceinline__ void mma16816(float& c0, float& c1, float& c2, float& c3,
                                         uint32_t a0, uint32_t a1, uint32_t a2, uint32_t a3,
                                         uint32_t b0, uint32_t b1) {
    asm volatile("mma.sync.aligned.m16n8k16.row.col.f32.bf16.bf16.f32 "
                 "{%0,%1,%2,%3}, {%4,%5,%6,%7}, {%8,%9}, {%0,%1,%2,%3};"
                 : "+f"(c0), "+f"(c1), "+f"(c2), "+f"(c3)
                 : "r"(a0), "r"(a1), "r"(a2), "r"(a3), "r"(b0), "r"(b1));
}
__device__ __forceinline__ uint32_t pack_bf16x2(float lo, float hi) {
    __nv_bfloat162 p = __floats2bfloat162_rn(lo, hi);
    return *reinterpret_cast<uint32_t*>(&p);
}
__device__ __forceinline__ uint32_t swz(int row, int x) {
    return (uint32_t)(row * 128 + (x ^ ((row & 7) << 4)));
}
__device__ __forceinline__ uint32_t swzH(int row, int x) {
    return (uint32_t)(row * 256 + (x ^ ((row & 7) << 4)));
}

// ---------------------------------------------------------------------------
// Persistent split-bf16 HMMA GEMM (unchanged from R13/R15).
// ---------------------------------------------------------------------------
namespace tg {
constexpr int K   = 8192;
constexpr int KT  = 64;
constexpr uint32_t SZ_A = 64 * 128;
constexpr uint32_t SZ_B = 128 * 128;
constexpr uint32_t STG  = 2 * SZ_A + 2 * SZ_B;   // 49152
constexpr uint32_t SMEM_TOTAL = 2 * STG;         // 98304
}

__global__ __launch_bounds__(256, 2) void tgemm_persist(
    const __nv_bfloat16* __restrict__ Ahi, const __nv_bfloat16* __restrict__ Alo,
    const __nv_bfloat16* __restrict__ Bhi, const __nv_bfloat16* __restrict__ Blo,
    float* __restrict__ out, int cbShift, int nbN, int G)
{
    using namespace tg;
    extern __shared__ char smem[];
    const uint32_t sb  = smem_to_u32(smem);
    const int tid  = threadIdx.x;
    const int lane = tid & 31;
    const int wid  = tid >> 5;
    const int wm   = wid >> 2;
    const int wn   = wid & 3;

    const int U = nbN * 128 * 128;
    const int uStart = (int)(((long)U * blockIdx.x) / G);
    const int uEnd   = (int)(((long)U * (blockIdx.x + 1)) / G);
    if (uStart >= uEnd) return;

    const int c0r = tid >> 3;
    const int c0s = tid & 7;

    float acc[2][4][4];
#pragma unroll
    for (int i = 0; i < 2; i++)
#pragma unroll
        for (int j = 0; j < 4; j++)
#pragma unroll
            for (int q2 = 0; q2 < 4; q2++) acc[i][j][q2] = 0.f;

    const int q  = lane >> 3;
    const int r8 = lane & 7;
    const int a_row_off = wm * 32 + r8 + (q & 1) * 8;
    const int a_k_off   = (q >> 1) * 16;
    const int b_row_off = wn * 32 + r8 + (q >> 1) * 8;
    const int b_k_off   = (q & 1) * 16;

#define LOAD_UNIT(ST, UU)                                                      \
    do {                                                                       \
        const int tile_ = (UU) >> 7;                                           \
        const int m0_   = (tile_ & 127) * 64;                                  \
        const int n0_   = (tile_ >> 7) * 128;                                  \
        const int k0_   = ((UU) & 127) * KT;                                   \
        const uint32_t base_ = sb + (uint32_t)(ST) * STG;                      \
        const uint32_t oA0_ = swz(c0r,      c0s * 16);                         \
        const uint32_t oA1_ = swz(c0r + 32, c0s * 16);                         \
        const int ga0_ = (m0_ + c0r)      * K + k0_ + c0s * 8;                 \
        const int ga1_ = (m0_ + c0r + 32) * K + k0_ + c0s * 8;                 \
        cp_async16(base_ + oA0_,        Ahi + ga0_);                           \
        cp_async16(base_ + oA1_,        Ahi + ga1_);                           \
        cp_async16(base_ + SZ_A + oA0_, Alo + ga0_);                           \
        cp_async16(base_ + SZ_A + oA1_, Alo + ga1_);                           \
        const uint32_t bB_ = base_ + 2 * SZ_A;                                 \
        _Pragma("unroll")                                                      \
        for (int rr_ = 0; rr_ < 4; rr_++) {                                    \
            const int brow_ = c0r + rr_ * 32;                                  \
            const uint32_t oB_ = swz(brow_, c0s * 16);                         \
            const int gb_ = (n0_ + brow_) * K + k0_ + c0s * 8;                 \
            cp_async16(bB_ + oB_,        Bhi + gb_);                           \
            cp_async16(bB_ + SZ_B + oB_, Blo + gb_);                           \
        }                                                                      \
        cp_async_commit();                                                     \
    } while (0)

    LOAD_UNIT(uStart & 1, uStart);

    for (int u = uStart; u < uEnd; u++) {
        if (u + 1 < uEnd) {
            LOAD_UNIT((u + 1) & 1, u + 1);
            cp_async_wait<1>();
        } else {
            cp_async_wait<0>();
        }
        __syncthreads();

        const uint32_t base = sb + (uint32_t)(u & 1) * STG;
        const uint32_t aHB = base;
        const uint32_t aLB = base + SZ_A;
        const uint32_t bHB = base + 2 * SZ_A;
        const uint32_t bLB = base + 2 * SZ_A + SZ_B;

#pragma unroll
        for (int s = 0; s < 4; s++) {
            const int kb = s * 32;
            uint32_t ah[2][4], al[2][4], bh[2][4], bl[2][4];
#pragma unroll
            for (int mi = 0; mi < 2; mi++) {
                const uint32_t ad = swz(a_row_off + mi * 16, kb + a_k_off);
                ldsm_x4(ah[mi][0], ah[mi][1], ah[mi][2], ah[mi][3], aHB + ad);
                ldsm_x4(al[mi][0], al[mi][1], al[mi][2], al[mi][3], aLB + ad);
            }
#pragma unroll
            for (int ni = 0; ni < 2; ni++) {
                const uint32_t bd = swz(b_row_off + ni * 16, kb + b_k_off);
                ldsm_x4(bh[ni][0], bh[ni][1], bh[ni][2], bh[ni][3], bHB + bd);
                ldsm_x4(bl[ni][0], bl[ni][1], bl[ni][2], bl[ni][3], bLB + bd);
            }
#pragma unroll
            for (int mi = 0; mi < 2; mi++)
#pragma unroll
                for (int nj = 0; nj < 4; nj++) {
                    const int g = nj >> 1, h = (nj & 1) * 2;
                    float* c = acc[mi][nj];
                    mma16816(c[0], c[1], c[2], c[3],
                             ah[mi][0], ah[mi][1], ah[mi][2], ah[mi][3],
                             bh[g][h], bh[g][h + 1]);
                }
#pragma unroll
            for (int mi = 0; mi < 2; mi++)
#pragma unroll
                for (int nj = 0; nj < 4; nj++) {
                    const int g = nj >> 1, h = (nj & 1) * 2;
                    float* c = acc[mi][nj];
                    mma16816(c[0], c[1], c[2], c[3],
                             al[mi][0], al[mi][1], al[mi][2], al[mi][3],
                             bh[g][h], bh[g][h + 1]);
                }
#pragma unroll
            for (int mi = 0; mi < 2; mi++)
#pragma unroll
                for (int nj = 0; nj < 4; nj++) {
                    const int g = nj >> 1, h = (nj & 1) * 2;
                    float* c = acc[mi][nj];
                    mma16816(c[0], c[1], c[2], c[3],
                             ah[mi][0], ah[mi][1], ah[mi][2], ah[mi][3],
                             bl[g][h], bl[g][h + 1]);
                }
        }

        if (u + 1 == uEnd || ((u + 1) & 127) == 0) {
            const int tile = u >> 7;
            const int m0 = (tile & 127) * 64;
            const int n0 = (tile >> 7) * 128;
            const int CB = 1 << cbShift;
#pragma unroll
            for (int mi = 0; mi < 2; mi++) {
                const int row = m0 + wm * 32 + mi * 16 + (lane >> 2);
#pragma unroll
                for (int nj = 0; nj < 4; nj++) {
                    const int g = n0 + wn * 32 + nj * 8 + 2 * (lane & 3);
                    const int b = g >> cbShift;
                    const int c = g & (CB - 1);
                    const int base0 = (b * 8192 + row) * CB + c;
                    atomicAdd(out + base0,              acc[mi][nj][0]);
                    atomicAdd(out + base0 + 1,          acc[mi][nj][1]);
                    atomicAdd(out + base0 + 8 * CB,     acc[mi][nj][2]);
                    atomicAdd(out + base0 + 8 * CB + 1, acc[mi][nj][3]);
                    acc[mi][nj][0] = acc[mi][nj][1] = 0.f;
                    acc[mi][nj][2] = acc[mi][nj][3] = 0.f;
                }
            }
        }
        __syncthreads();
    }
#undef LOAD_UNIT
}

// ---------------------------------------------------------------------------
// Fused 2-layer MLP body (96KB smem, W region multiplexed W1->W2).
// modes: 0/2/4: outF only; 1: outK (CB=64) + zbuf; 3: threshold + outK (CB=128)
// ---------------------------------------------------------------------------
namespace fm {
constexpr uint32_t O_W1H = 0;
constexpr uint32_t O_W1L = 16384;
constexpr uint32_t O_W2H = 0;
constexpr uint32_t O_W2L = 16384;
constexpr uint32_t O_XF  = 32768;
constexpr uint32_t O_XH  = 65536;
constexpr uint32_t O_XL  = 81920;
constexpr uint32_t O_HH  = 32768;
constexpr uint32_t O_HL  = 65536;
constexpr uint32_t O_T   = 32768;
constexpr uint32_t SMEM_TOTAL = 98304;
}

__device__ __forceinline__ void fmlp_body(
    char* smem, uint32_t sb, int tid, long m0,
    const float* __restrict__ X, int ldx,
    const __nv_bfloat16* __restrict__ W1h, const __nv_bfloat16* __restrict__ W1l,
    const float* __restrict__ b1,
    const __nv_bfloat16* __restrict__ W2h, const __nv_bfloat16* __restrict__ W2l,
    const float* __restrict__ b2,
    const float* __restrict__ add,
    float* __restrict__ outF,
    __nv_bfloat16* __restrict__ outKh, __nv_bfloat16* __restrict__ outKl,
    const float* __restrict__ alphaPtr, int mode,
    float* __restrict__ zbuf, int zcols)
{
    using namespace fm;
    const int lane = tid & 31;
    const int wid  = tid >> 5;

    // phase-1 loads: W1 hi/lo + X fp32
    {
#pragma unroll
        for (int j = 0; j < 4; j++) {
            const int idx = tid + j * 256;
            const int row = idx >> 3, seg = idx & 7;
            const uint32_t o = swz(row, seg * 16);
            cp_async16(sb + O_W1H + o, W1h + row * 64 + seg * 8);
            cp_async16(sb + O_W1L + o, W1l + row * 64 + seg * 8);
        }
#pragma unroll
        for (int j = 0; j < 8; j++) {
            const int idx = tid + j * 256;
            const int row = idx >> 4, seg = idx & 15;
            cp_async16(sb + O_XF + row * 256 + seg * 16,
                       X + (m0 + row) * (long)ldx + seg * 4);
        }
        cp_async_commit();
        cp_async_wait<0>();
        __syncthreads();
    }

#pragma unroll
    for (int j = 0; j < 16; j++) {
        const int p = tid + j * 256;
        const int row = p >> 5, kp = p & 31;
        const float2 v = *reinterpret_cast<const float2*>(smem + O_XF + row * 256 + kp * 8);
        const __nv_bfloat16 h0 = __float2bfloat16(v.x);
        const __nv_bfloat16 h1 = __float2bfloat16(v.y);
        const float l0 = v.x - __bfloat162float(h0);
        const float l1 = v.y - __bfloat162float(h1);
        const uint32_t oo = swz(row, kp * 4);
        *reinterpret_cast<uint32_t*>(smem + O_XH + oo) =
            ((uint32_t)*reinterpret_cast<const uint16_t*>(&h1) << 16) |
             (uint32_t)*reinterpret_cast<const uint16_t*>(&h0);
        *reinterpret_cast<uint32_t*>(smem + O_XL + oo) = pack_bf16x2(l0, l1);
    }
    __syncthreads();

    if (zbuf != nullptr) {
        float4* zp = reinterpret_cast<float4*>(zbuf + m0 * zcols);
        const int tot = 128 * zcols / 4;
        const float4 z4 = make_float4(0.f, 0.f, 0.f, 0.f);
        for (int i = tid; i < tot; i += 256) zp[i] = z4;
    }

    const int q  = lane >> 3;
    const int r8 = lane & 7;

    // GEMM1: warps 2m x 4n, warp tile 64x32
    float acc1[4][4][4];
#pragma unroll
    for (int i = 0; i < 4; i++)
#pragma unroll
        for (int j = 0; j < 4; j++)
#pragma unroll
            for (int k = 0; k < 4; k++) acc1[i][j][k] = 0.f;
    {
        const int wm1 = wid >> 2, wn1 = wid & 3;
        const int ar = wm1 * 64 + r8 + (q & 1) * 8;
        const int ax = (q >> 1) * 16;
        const int br = wn1 * 32 + r8 + (q >> 1) * 8;
        const int bx = (q & 1) * 16;
#pragma unroll
        for (int s = 0; s < 4; s++) {
            const int kx = s * 32;
            uint32_t bh[2][4], bl[2][4];
#pragma unroll
            for (int ni = 0; ni < 2; ni++) {
                const uint32_t bd = swz(br + ni * 16, kx + bx);
                ldsm_x4(bh[ni][0], bh[ni][1], bh[ni][2], bh[ni][3], sb + O_W1H + bd);
                ldsm_x4(bl[ni][0], bl[ni][1], bl[ni][2], bl[ni][3], sb + O_W1L + bd);
            }
#pragma unroll
            for (int mi = 0; mi < 4; mi++) {
                uint32_t ah[4], al[4];
                const uint32_t ad = swz(ar + mi * 16, kx + ax);
                ldsm_x4(ah[0], ah[1], ah[2], ah[3], sb + O_XH + ad);
                ldsm_x4(al[0], al[1], al[2], al[3], sb + O_XL + ad);
#pragma unroll
                for (int nj = 0; nj < 4; nj++) {
                    const int g = nj >> 1, h = (nj & 1) * 2;
                    float* c = acc1[mi][nj];
                    mma16816(c[0], c[1], c[2], c[3],
                             ah[0], ah[1], ah[2], ah[3], bh[g][h], bh[g][h + 1]);
                    mma16816(c[0], c[1], c[2], c[3],
                             al[0], al[1], al[2], al[3], bh[g][h], bh[g][h + 1]);
                    mma16816(c[0], c[1], c[2], c[3],
                             ah[0], ah[1], ah[2], ah[3], bl[g][h], bl[g][h + 1]);
                }
            }
        }
    }
    __syncthreads();

    // W2 loads into W region, overlapped with H store
    {
#pragma unroll
        for (int j = 0; j < 4; j++) {
            const int idx = tid + j * 256;
            const int row = idx >> 4, seg = idx & 15;
            const uint32_t o = swzH(row, seg * 16);
            cp_async16(sb + O_W2H + o, W2h + row * 128 + seg * 8);
            cp_async16(sb + O_W2L + o, W2l + row * 128 + seg * 8);
        }
        cp_async_commit();
    }

    // +b1, relu, split, store H
    {
        const int wm1 = wid >> 2, wn1 = wid & 3;
#pragma unroll
        for (int mi = 0; mi < 4; mi++) {
            const int row0 = wm1 * 64 + mi * 16 + (lane >> 2);
#pragma unroll
            for (int nj = 0; nj < 4; nj++) {
                const int n = wn1 * 32 + nj * 8 + 2 * (lane & 3);
                const float bb0 = __ldg(b1 + n);
                const float bb1 = __ldg(b1 + n + 1);
                float v0 = fmaxf(acc1[mi][nj][0] + bb0, 0.f);
                float v1 = fmaxf(acc1[mi][nj][1] + bb1, 0.f);
                float v2 = fmaxf(acc1[mi][nj][2] + bb0, 0.f);
                float v3 = fmaxf(acc1[mi][nj][3] + bb1, 0.f);
                const __nv_bfloat16 h0 = __float2bfloat16(v0);
                const __nv_bfloat16 h1 = __float2bfloat16(v1);
                const __nv_bfloat16 h2 = __float2bfloat16(v2);
                const __nv_bfloat16 h3 = __float2bfloat16(v3);
                const uint32_t o0 = swzH(row0,     n * 2);
                const uint32_t o1 = swzH(row0 + 8, n * 2);
                *reinterpret_cast<uint32_t*>(smem + O_HH + o0) =
                    ((uint32_t)*reinterpret_cast<const uint16_t*>(&h1) << 16) |
                     (uint32_t)*reinterpret_cast<const uint16_t*>(&h0);
                *reinterpret_cast<uint32_t*>(smem + O_HH + o1) =
                    ((uint32_t)*reinterpret_cast<const uint16_t*>(&h3) << 16) |
                     (uint32_t)*reinterpret_cast<const uint16_t*>(&h2);
                *reinterpret_cast<uint32_t*>(smem + O_HL + o0) =
                    pack_bf16x2(v0 - __bfloat162float(h0), v1 - __bfloat162float(h1));
                *reinterpret_cast<uint32_t*>(smem + O_HL + o1) =
                    pack_bf16x2(v2 - __bfloat162float(h2), v3 - __bfloat162float(h3));
            }
        }
    }
    cp_async_wait<0>();
    __syncthreads();

    // GEMM2: warps 4m x 2n, warp tile 32x32
    float acc2[2][4][4];
#pragma unroll
    for (int i = 0; i < 2; i++)
#pragma unroll
        for (int j = 0; j < 4; j++)
#pragma unroll
            for (int k = 0; k < 4; k++) acc2[i][j][k] = 0.f;
    const int wm2 = wid >> 1, wn2 = wid & 1;
    {
        const int ar = wm2 * 32 + r8 + (q & 1) * 8;
        const int ax = (q >> 1) * 16;
        const int br = wn2 * 32 + r8 + (q >> 1) * 8;
        const int bx = (q & 1) * 16;
#pragma unroll
        for (int s = 0; s < 8; s++) {
            const int kx = s * 32;
            uint32_t ah[2][4], al[2][4], bh[2][4], bl[2][4];
#pragma unroll
            for (int mi = 0; mi < 2; mi++) {
                const uint32_t ad = swzH(ar + mi * 16, kx + ax);
                ldsm_x4(ah[mi][0], ah[mi][1], ah[mi][2], ah[mi][3], sb + O_HH + ad);
                ldsm_x4(al[mi][0], al[mi][1], al[mi][2], al[mi][3], sb + O_HL + ad);
            }
#pragma unroll
            for (int ni = 0; ni < 2; ni++) {
                const uint32_t bd = swzH(br + ni * 16, kx + bx);
                ldsm_x4(bh[ni][0], bh[ni][1], bh[ni][2], bh[ni][3], sb + O_W2H + bd);
                ldsm_x4(bl[ni][0], bl[ni][1], bl[ni][2], bl[ni][3], sb + O_W2L + bd);
            }
#pragma unroll
            for (int mi = 0; mi < 2; mi++)
#pragma unroll
                for (int nj = 0; nj < 4; nj++) {
                    const int g = nj >> 1, h = (nj & 1) * 2;
                    float* c = acc2[mi][nj];
                    mma16816(c[0], c[1], c[2], c[3],
                             ah[mi][0], ah[mi][1], ah[mi][2], ah[mi][3],
                             bh[g][h], bh[g][h + 1]);
                    mma16816(c[0], c[1], c[2], c[3],
                             al[mi][0], al[mi][1], al[mi][2], al[mi][3],
                             bh[g][h], bh[g][h + 1]);
                    mma16816(c[0], c[1], c[2], c[3],
                             ah[mi][0], ah[mi][1], ah[mi][2], ah[mi][3],
                             bl[g][h], bl[g][h + 1]);
                }
        }
    }
    __syncthreads();

    const float alpha = (mode == 3) ? __ldg(alphaPtr) : 0.f;
    const uint32_t tSz = (mode == 3) ? 32768u : 16384u;
#pragma unroll
    for (int mi = 0; mi < 2; mi++) {
        const int  rl0 = wm2 * 32 + mi * 16 + (lane >> 2);
#pragma unroll
        for (int nj = 0; nj < 4; nj++) {
            const int c = wn2 * 32 + nj * 8 + 2 * (lane & 3);
            const float bb0 = __ldg(b2 + c);
            const float bb1 = __ldg(b2 + c + 1);
            float v[4];
            v[0] = acc2[mi][nj][0] + bb0;
            v[1] = acc2[mi][nj][1] + bb1;
            v[2] = acc2[mi][nj][2] + bb0;
            v[3] = acc2[mi][nj][3] + bb1;
            if (add != nullptr) {
                const float2 a0 = *reinterpret_cast<const float2*>(add + (m0 + rl0) * 64 + c);
                const float2 a1 = *reinterpret_cast<const float2*>(add + (m0 + rl0 + 8) * 64 + c);
                v[0] += a0.x; v[1] += a0.y; v[2] += a1.x; v[3] += a1.y;
            }
            if (outF != nullptr) {
                *reinterpret_cast<float2*>(outF + (m0 + rl0) * 64 + c)     = make_float2(v[0], v[1]);
                *reinterpret_cast<float2*>(outF + (m0 + rl0 + 8) * 64 + c) = make_float2(v[2], v[3]);
            }
            if (mode == 1 || mode == 3) {
#pragma unroll
                for (int e = 0; e < 4; e++) {
                    const int rl = rl0 + (e >> 1) * 8;
                    const int cc = c + (e & 1);
                    const float s = v[e];
                    const __nv_bfloat16 hi = __float2bfloat16(s);
                    *reinterpret_cast<__nv_bfloat16*>(smem + O_T + cc * 256 + rl * 2) = hi;
                    *reinterpret_cast<__nv_bfloat16*>(smem + O_T + tSz + cc * 256 + rl * 2) =
                        __float2bfloat16(s - __bfloat162float(hi));
                    if (mode == 3) {
                        const float z = (s > alpha) ? (s - alpha)
                                                    : ((s < -alpha) ? (s + alpha) : 0.f);
                        const __nv_bfloat16 zh = __float2bfloat16(z);
                        *reinterpret_cast<__nv_bfloat16*>(smem + O_T + (64 + cc) * 256 + rl * 2) = zh;
                        *reinterpret_cast<__nv_bfloat16*>(smem + O_T + tSz + (64 + cc) * 256 + rl * 2) =
                            __float2bfloat16(z - __bfloat162float(zh));
                    }
                }
            }
        }
    }

    if (mode == 1 || mode == 3) {
        __syncthreads();
        const int CB = (mode == 3) ? 128 : 64;
        const long bb = m0 >> 13;
        const long k0 = m0 & 8191;
        const int total = CB * 16 * 2;
        for (int idx = tid; idx < total; idx += 256) {
            const int arr = idx >= CB * 16;
            const int rem = arr ? idx - CB * 16 : idx;
            const int j   = rem >> 4;
            const int s16 = rem & 15;
            const uint4 val = *reinterpret_cast<const uint4*>(
                smem + O_T + (uint32_t)arr * tSz + j * 256 + s16 * 16);
            __nv_bfloat16* dst = (arr ? outKl : outKh) +
                ((long)(bb * CB + j)) * 8192 + k0 + s16 * 8;
            *reinterpret_cast<uint4*>(dst) = val;
        }
    }
}

// single-MLP kernel (bx prologue / final output)
__global__ __launch_bounds__(256, 2) void fmlp_one(
    const float* __restrict__ X, int ldx,
    const __nv_bfloat16* __restrict__ W1h, const __nv_bfloat16* __restrict__ W1l,
    const float* __restrict__ b1,
    const __nv_bfloat16* __restrict__ W2h, const __nv_bfloat16* __restrict__ W2l,
    const float* __restrict__ b2,
    float* __restrict__ outF)
{
    extern __shared__ char smem[];
    fmlp_body(smem, smem_to_u32(smem), threadIdx.x, (long)blockIdx.x * 128,
              X, ldx, W1h, W1l, b1, W2h, W2l, b2,
              nullptr, outF, nullptr, nullptr, nullptr, 0, nullptr, 0);
}

// dual-phase kernel: phase A (mlpA +bx -> Y, zero t64), phase E (mlpE -> e,
// zero Asz)
__global__ __launch_bounds__(256, 2) void fmlp_AE(
    const float* __restrict__ Asz,
    const __nv_bfloat16* __restrict__ WA1h, const __nv_bfloat16* __restrict__ WA1l,
    const float* __restrict__ bA1,
    const __nv_bfloat16* __restrict__ WA2h, const __nv_bfloat16* __restrict__ WA2l,
    const float* __restrict__ bA2,
    const __nv_bfloat16* __restrict__ WE1h, const __nv_bfloat16* __restrict__ WE1l,
    const float* __restrict__ bE1,
    const __nv_bfloat16* __restrict__ WE2h, const __nv_bfloat16* __restrict__ WE2l,
    const float* __restrict__ bE2,
    const float* __restrict__ bx,
    __nv_bfloat16* __restrict__ Yhi, __nv_bfloat16* __restrict__ Ylo,
    float* __restrict__ e,
    float* __restrict__ t64, float* __restrict__ AszZ)
{
    extern __shared__ char smem[];
    const uint32_t sb = smem_to_u32(smem);
    const long m0 = (long)blockIdx.x * 128;
    // phase A: y = mlpA(Asz[:, :64]) + bx -> Y K-major; zero t64 rows
    fmlp_body(smem, sb, threadIdx.x, m0,
              Asz, 128, WA1h, WA1l, bA1, WA2h, WA2l, bA2,
              bx, nullptr, Yhi, Ylo, nullptr, 1, t64, 64);
    __syncthreads();
    // phase E: e = mlpE(Asz[:, 64:]); zero Asz rows (after X load)
    fmlp_body(smem, sb, threadIdx.x, m0,
              Asz + 64, 128, WE1h, WE1l, bE1, WE2h, WE2l, bE2,
              nullptr, e, nullptr, nullptr, nullptr, 2, AszZ, 128);
}

// D3 kernel: s = mlpD(t64) + e, threshold -> SZ; outF optional (last iter)
__global__ __launch_bounds__(256, 2) void fmlp_D3(
    const float* __restrict__ t64,
    const __nv_bfloat16* __restrict__ W1h, const __nv_bfloat16* __restrict__ W1l,
    const float* __restrict__ b1,
    const __nv_bfloat16* __restrict__ W2h, const __nv_bfloat16* __restrict__ W2l,
    const float* __restrict__ b2,
    const float* __restrict__ e,
    float* __restrict__ outF,
    __nv_bfloat16* __restrict__ SZhi, __nv_bfloat16* __restrict__ SZlo,
    const float* __restrict__ alphaPtr)
{
    extern __shared__ char smem[];
    fmlp_body(smem, smem_to_u32(smem), threadIdx.x, (long)blockIdx.x * 128,
              t64, 64, W1h, W1l, b1, W2h, W2l, b2,
              e, outF, SZhi, SZlo, alphaPtr, 3, nullptr, 0);
}

// ---------------------------------------------------------------------------
__global__ __launch_bounds__(256) void prep_w_kernel(
    const float* __restrict__ W1, const float* __restrict__ W2,
    __nv_bfloat16* __restrict__ w1h, __nv_bfloat16* __restrict__ w1l,
    __nv_bfloat16* __restrict__ w2h, __nv_bfloat16* __restrict__ w2l)
{
    const int id = blockIdx.x * 256 + threadIdx.x;
    if (id < 8192) {
        const int n = id >> 6, k = id & 63;
        const float v = W1[k * 128 + n];
        const __nv_bfloat16 h = __float2bfloat16(v);
        w1h[id] = h;
        w1l[id] = __float2bfloat16(v - __bfloat162float(h));
    } else if (id < 16384) {
        const int i2 = id - 8192;
        const int n = i2 >> 7, k = i2 & 127;
        const float v = W2[k * 64 + n];
        const __nv_bfloat16 h = __float2bfloat16(v);
        w2h[i2] = h;
        w2l[i2] = __float2bfloat16(v - __bfloat162float(h));
    }
}

__global__ __launch_bounds__(256) void split_A_kernel(const float* __restrict__ A)
{
    const long n = (long)cfg::N * cfg::N;
    long idx = ((long)blockIdx.x * blockDim.x + threadIdx.x) * 4;
    if (idx >= n) return;
    float4 v = *reinterpret_cast<const float4*>(A + idx);
    float f[4] = {v.x, v.y, v.z, v.w};
#pragma unroll
    for (int q = 0; q < 4; q++) {
        __nv_bfloat16 hi = __float2bfloat16(f[q]);
        g_Ahi[idx + q] = hi;
        g_Alo[idx + q] = __float2bfloat16(f[q] - __bfloat162float(hi));
    }
}

__global__ __launch_bounds__(256) void split_transpose_kernel(
    const float* __restrict__ X,
    __nv_bfloat16* __restrict__ oh, __nv_bfloat16* __restrict__ ol)
{
    __shared__ float tile[32][33];
    const int k0 = blockIdx.x * 32;
    const int j0 = blockIdx.y * 32;
    const int b  = j0 / 64;
    const int c0 = j0 % 64;
    const int tx = threadIdx.x, ty = threadIdx.y;

    for (int r = ty; r < 32; r += 8)
        tile[r][tx] = X[((long)b * cfg::N + k0 + r) * 64 + c0 + tx];
    __syncthreads();
    for (int r = ty; r < 32; r += 8) {
        const float v = tile[tx][r];
        const __nv_bfloat16 hi = __float2bfloat16(v);
        const long o = (long)(j0 + r) * cfg::N + k0 + tx;
        oh[o] = hi;
        ol[o] = __float2bfloat16(v - __bfloat162float(hi));
    }
}

__global__ __launch_bounds__(256) void zero_buf_kernel(float* __restrict__ p, long n)
{
    long idx = ((long)blockIdx.x * blockDim.x + threadIdx.x) * 4;
    if (idx < n) *reinterpret_cast<float4*>(p + idx) = make_float4(0.f, 0.f, 0.f, 0.f);
}

// ============================================================================
extern "C" void kernel_launch(void* const* d_in, const int* in_sizes, int n_in,
                              void* d_out, int out_size)
{
    using namespace cfg;
    const float* x_c   = (const float*)d_in[0];
    const float* A     = (const float*)d_in[1];
    const float* alpha = (const float*)d_in[2];
    const float* WA1 = (const float*)d_in[3];
    const float* bA1 = (const float*)d_in[4];
    const float* WA2 = (const float*)d_in[5];
    const float* bA2 = (const float*)d_in[6];
    const float* WB1 = (const float*)d_in[7];
    const float* bB1 = (const float*)d_in[8];
    const float* WB2 = (const float*)d_in[9];
    const float* bB2 = (const float*)d_in[10];
    const float* WD1 = (const float*)d_in[11];
    const float* bD1 = (const float*)d_in[12];
    const float* WD2 = (const float*)d_in[13];
    const float* bD2 = (const float*)d_in[14];
    const float* WE1 = (const float*)d_in[15];
    const float* bE1 = (const float*)d_in[16];
    const float* WE2 = (const float*)d_in[17];
    const float* bE2 = (const float*)d_in[18];
    float* out = (float*)d_out;

    float *Asz, *t64, *bxp, *ep;
    __nv_bfloat16 *Ahi, *Alo, *Yhi, *Ylo, *SZhi, *SZlo;
    __nv_bfloat16 *W1h, *W1l, *W2h, *W2l;
    cudaGetSymbolAddress((void**)&Asz,  g_Asz);
    cudaGetSymbolAddress((void**)&t64,  g_t64);
    cudaGetSymbolAddress((void**)&bxp,  g_bx);
    cudaGetSymbolAddress((void**)&ep,   g_e);
    cudaGetSymbolAddress((void**)&Ahi,  g_Ahi);
    cudaGetSymbolAddress((void**)&Alo,  g_Alo);
    cudaGetSymbolAddress((void**)&Yhi,  g_Yhi);
    cudaGetSymbolAddress((void**)&Ylo,  g_Ylo);
    cudaGetSymbolAddress((void**)&SZhi, g_SZhi);
    cudaGetSymbolAddress((void**)&SZlo, g_SZlo);
    cudaGetSymbolAddress((void**)&W1h,  g_W1h);
    cudaGetSymbolAddress((void**)&W1l,  g_W1l);
    cudaGetSymbolAddress((void**)&W2h,  g_W2h);
    cudaGetSymbolAddress((void**)&W2l,  g_W2l);

    int smCount = 148;
    cudaDeviceGetAttribute(&smCount, cudaDevAttrMultiProcessorCount, 0);
    const int G = 2 * smCount;

    cudaFuncSetAttribute(tgemm_persist, cudaFuncAttributeMaxDynamicSharedMemorySize,
                         tg::SMEM_TOTAL);
    cudaFuncSetAttribute(fmlp_one, cudaFuncAttributeMaxDynamicSharedMemorySize,
                         fm::SMEM_TOTAL);
    cudaFuncSetAttribute(fmlp_AE, cudaFuncAttributeMaxDynamicSharedMemorySize,
                         fm::SMEM_TOTAL);
    cudaFuncSetAttribute(fmlp_D3, cudaFuncAttributeMaxDynamicSharedMemorySize,
                         fm::SMEM_TOTAL);

    auto w1h = [&](int i) { return W1h + (long)i * 128 * 64; };
    auto w1l = [&](int i) { return W1l + (long)i * 128 * 64; };
    auto w2h = [&](int i) { return W2h + (long)i * 64 * 128; };
    auto w2l = [&](int i) { return W2l + (long)i * 64 * 128; };

    const dim3 blk(256);
    const dim3 gF((unsigned)(ROWS / 128), 1, 1);
    const dim3 tblk(32, 8, 1);
    const dim3 gTr64(N / 32, (BATCH * 64) / 32, 1);

    const long nT64  = ROWS * 64;
    const long nAsz  = ROWS * 128;
    const unsigned zT = (unsigned)((nT64 / 4 + 255) / 256);
    const unsigned zA = (unsigned)((nAsz / 4 + 255) / 256);

    float* sOut = out + ROWS * 64;

    // --- one-time prep ---
    {
        const long n4 = ((long)N * N) / 4;
        split_A_kernel<<<(unsigned)((n4 + 255) / 256), blk>>>(A);
    }
    prep_w_kernel<<<64, blk>>>(WA1, WA2, w1h(0), w1l(0), w2h(0), w2l(0));
    prep_w_kernel<<<64, blk>>>(WB1, WB2, w1h(1), w1l(1), w2h(1), w2l(1));
    prep_w_kernel<<<64, blk>>>(WD1, WD2, w1h(2), w1l(2), w2h(2), w2l(2));
    prep_w_kernel<<<64, blk>>>(WE1, WE2, w1h(3), w1l(3), w2h(3), w2l(3));
    zero_buf_kernel<<<zT, blk>>>(t64, nT64);
    zero_buf_kernel<<<zA, blk>>>(Asz, nAsz);

    // --- t64 = A @ x_c ---
    split_transpose_kernel<<<gTr64, tblk>>>(x_c, Yhi, Ylo);
    tgemm_persist<<<G, blk, tg::SMEM_TOTAL>>>(Ahi, Alo, Yhi, Ylo, t64, 6, 2, G);
    // --- bx = mlpB(t64) ---
    fmlp_one<<<gF, blk, fm::SMEM_TOTAL>>>(t64, 64, w1h(1), w1l(1), bB1,
                                          w2h(1), w2l(1), bB2, bxp);

    for (int it = 0; it < ITERS; it++) {
        if (it > 0) {
            tgemm_persist<<<G, blk, tg::SMEM_TOTAL>>>(Ahi, Alo, SZhi, SZlo, Asz, 7, 4, G);
        }
        // phase A: y -> Y (zero t64); phase E: e (zero Asz)
        fmlp_AE<<<gF, blk, fm::SMEM_TOTAL>>>(
            Asz, w1h(0), w1l(0), bA1, w2h(0), w2l(0), bA2,
            w1h(3), w1l(3), bE1, w2h(3), w2l(3), bE2,
            bxp, Yhi, Ylo, ep, t64, Asz);
        // t64 = A @ y
        tgemm_persist<<<G, blk, tg::SMEM_TOTAL>>>(Ahi, Alo, Yhi, Ylo, t64, 6, 2, G);
        // s = mlpD(t64) + e; threshold -> SZ; outF only on final iteration
        float* sDst = (it == ITERS - 1) ? sOut : nullptr;
        fmlp_D3<<<gF, blk, fm::SMEM_TOTAL>>>(
            t64, w1h(2), w1l(2), bD1, w2h(2), w2l(2), bD2,
            ep, sDst, SZhi, SZlo, alpha);
    }

    // --- out[:R*64] = mlpD(s) ; s already at out[R*64:] ---
    fmlp_one<<<gF, blk, fm::SMEM_TOTAL>>>(sOut, 64, w1h(2), w1l(2), bD1,
                                          w2h(2), w2l(2), bD2, out);
}